// round 5
// baseline (speedup 1.0000x reference)
#include <cuda_runtime.h>
#include <cuda_fp16.h>
#include <cstdint>

#define NNODES 10000
#define NEDGES 320000
#define CH     256

// ---- scratch (static device allocations; no cudaMalloc allowed) ----
__device__ __align__(16) __half g_xhi[NNODES * 64];
__device__ __align__(16) __half g_xlo[NNODES * 64];
__device__ __align__(16) __half g_Hhi[NNODES * CH];
__device__ __align__(16) __half g_Hlo[NNODES * CH];
__device__ __align__(16) __half g_Ahi[NNODES * CH];   // relu(agg) split, next-layer input
__device__ __align__(16) __half g_Alo[NNODES * CH];
__device__ __align__(16) __half g_AB [NNODES * 2 * CH];
__device__ __align__(16) __half g_Wlhi[3][CH * CH];
__device__ __align__(16) __half g_Wllo[3][CH * CH];
__device__ __align__(16) __half g_Wshi[3][2 * CH * CH];
__device__ __align__(16) __half g_Wslo[3][2 * CH * CH];
__device__ float g_bfull[3][2 * CH];
__device__ int g_rowptr[NNODES + 1];
__device__ int g_cnt[NNODES];
__device__ int g_col[NEDGES];

__device__ __forceinline__ uint32_t sptr(const void* p) {
    return (uint32_t)__cvta_generic_to_shared(p);
}
__device__ __forceinline__ void cpa16(uint32_t dst, const void* src, bool pred) {
    int sz = pred ? 16 : 0;
    asm volatile("cp.async.cg.shared.global [%0], [%1], 16, %2;"
                 :: "r"(dst), "l"(src), "r"(sz));
}
__device__ __forceinline__ void cpa_commit() {
    asm volatile("cp.async.commit_group;" ::: "memory");
}

// ============================================================================
// ONE fused conversion kernel: fp32 -> (hi,lo) fp16 for x, W_lin[3], W_s1[3]
// (repacked to uniform [512,256]), padded biases, and g_cnt zeroing.
// ============================================================================
#define SEG_X   (NNODES * 64)
#define SEG_E0  SEG_X
#define SEG_E1  (SEG_E0 + 16384)
#define SEG_E2  (SEG_E1 + 65536)
#define SEG_E3  (SEG_E2 + 65536)
#define SEG_E4  (SEG_E3 + 131072)
#define SEG_E5  (SEG_E4 + 131072)
#define SEG_E6  (SEG_E5 + 131072)
#define SEG_E7  (SEG_E6 + 512)
#define SEG_E8  (SEG_E7 + 512)
#define SEG_E9  (SEG_E8 + 512)
#define SEG_END (SEG_E9 + NNODES)

__global__ void __launch_bounds__(256) cvt_all(
    const float* __restrict__ x,
    const float* __restrict__ Wl1, const float* __restrict__ Wl2, const float* __restrict__ Wl3,
    const float* __restrict__ Ws1, const float* __restrict__ Ws2, const float* __restrict__ Ws3,
    const float* __restrict__ bs1, const float* __restrict__ bs2, const float* __restrict__ bs3)
{
    int i = blockIdx.x * blockDim.x + threadIdx.x;
    if (i >= SEG_END) return;
    if (i < SEG_E0) {
        float v = x[i];
        __half h = __float2half_rn(v);
        g_xhi[i] = h;
        g_xlo[i] = __float2half_rn(v - __half2float(h));
        return;
    }
    if (i < SEG_E3) {
        int l, j; const float* W;
        if (i < SEG_E1)      { l = 0; j = i - SEG_E0; W = Wl1; }
        else if (i < SEG_E2) { l = 1; j = i - SEG_E1; W = Wl2; }
        else                 { l = 2; j = i - SEG_E2; W = Wl3; }
        float v = W[j];
        __half h = __float2half_rn(v);
        g_Wlhi[l][j] = h;
        g_Wllo[l][j] = __float2half_rn(v - __half2float(h));
        return;
    }
    if (i < SEG_E6) {
        int l, j; const float* W;
        if (i < SEG_E4)      { l = 0; j = i - SEG_E3; W = Ws1; }
        else if (i < SEG_E5) { l = 1; j = i - SEG_E4; W = Ws2; }
        else                 { l = 2; j = i - SEG_E5; W = Ws3; }
        int r = j >> 8, k = j & 255;
        float v = (r < CH) ? W[r * 2 * CH + k] : W[(r - CH) * 2 * CH + CH + k];
        __half h = __float2half_rn(v);
        g_Wshi[l][j] = h;
        g_Wslo[l][j] = __float2half_rn(v - __half2float(h));
        return;
    }
    if (i < SEG_E9) {
        int l, j; const float* b;
        if (i < SEG_E7)      { l = 0; j = i - SEG_E6; b = bs1; }
        else if (i < SEG_E8) { l = 1; j = i - SEG_E7; b = bs2; }
        else                 { l = 2; j = i - SEG_E8; b = bs3; }
        g_bfull[l][j] = (j < CH) ? b[j] : 0.f;
        return;
    }
    g_cnt[i - SEG_E9] = 0;
}

// ============================================================================
// Tensor-core GEMM, split-fp16 (Markidis 3-term), pre-split operands:
//   out = (Ahi+Alo)[M,K] @ (Whi+Wlo)[NOUT,K]^T + bias  (lo*lo dropped)
// Virtual K' = 3K over regions: (Ahi,Whi), (Alo,Whi), (Ahi,Wlo).
// BM=128 BN=128 BK=32, 8 warps (2x4), warp tile 64x32, 3-stage cp.async,
// 64B smem rows swizzled (c ^= (row>>1)&3) -> conflict-free ldmatrix.
// OUTMODE 0: write hi/lo fp16 split. OUTMODE 1: single fp16.
// ============================================================================
template<int OUTMODE>
__global__ void __launch_bounds__(256) mma_gemm(
    const __half* __restrict__ Ahi, const __half* __restrict__ Alo,
    const __half* __restrict__ Whi, const __half* __restrict__ Wlo,
    const float* __restrict__ bias,
    __half* __restrict__ out0, __half* __restrict__ out1,
    int M, int K, int NOUT)
{
    constexpr int BM = 128, BN = 128, BK = 32, ST = 3;
    __shared__ __align__(16) __half sA[ST][BM * BK];   // 3 x 8 KB
    __shared__ __align__(16) __half sB[ST][BN * BK];   // 3 x 8 KB  (total 48 KB)

    const int tid  = threadIdx.x;
    const int lane = tid & 31;
    const int warp = tid >> 5;
    const int wm   = (warp & 1) * 64;
    const int wn   = (warp >> 1) * 32;
    const int bm   = blockIdx.x * BM;
    const int bn   = blockIdx.y * BN;
    const int nch  = (3 * K) / BK;

    float c[4][4][4];
    #pragma unroll
    for (int i = 0; i < 4; i++)
        #pragma unroll
        for (int j = 0; j < 4; j++)
            #pragma unroll
            for (int q = 0; q < 4; q++) c[i][j][q] = 0.f;

    auto issue = [&](int ch) {
        int buf = ch % ST;
        int k0v = ch * BK;
        int region = k0v / K;
        int kreal  = k0v - region * K;
        const __half* As = (region == 1) ? Alo : Ahi;
        const __half* Ws = (region == 2) ? Wlo : Whi;
        uint32_t baseA = sptr(&sA[buf][0]);
        uint32_t baseB = sptr(&sB[buf][0]);
        #pragma unroll
        for (int p = 0; p < 2; p++) {
            int idx = tid + p * 256;          // 0..511
            int row = idx >> 2;               // 0..127
            int cq  = idx & 3;                // 16B chunk
            int gm  = bm + row;
            bool ok = gm < M;
            const __half* src = As + (size_t)(ok ? gm : 0) * K + kreal + cq * 8;
            cpa16(baseA + row * 64 + ((cq ^ ((row >> 1) & 3)) << 4), src, ok);
        }
        #pragma unroll
        for (int p = 0; p < 2; p++) {
            int idx = tid + p * 256;
            int row = idx >> 2;
            int cq  = idx & 3;
            const __half* src = Ws + (size_t)(bn + row) * K + kreal + cq * 8;
            cpa16(baseB + row * 64 + ((cq ^ ((row >> 1) & 3)) << 4), src, true);
        }
        cpa_commit();
    };

    auto compute = [&](int buf) {
        uint32_t baseA = sptr(&sA[buf][0]);
        uint32_t baseB = sptr(&sB[buf][0]);
        #pragma unroll
        for (int kk = 0; kk < 2; kk++) {
            uint32_t bf[2][4];
            #pragma unroll
            for (int h = 0; h < 2; h++) {
                int row = wn + h * 16 + (lane & 15);
                int cq  = kk * 2 + (lane >> 4);
                uint32_t p = baseB + row * 64 + ((cq ^ ((row >> 1) & 3)) << 4);
                asm volatile("ldmatrix.sync.aligned.m8n8.x4.shared.b16 {%0,%1,%2,%3}, [%4];"
                             : "=r"(bf[h][0]), "=r"(bf[h][1]), "=r"(bf[h][2]), "=r"(bf[h][3]) : "r"(p));
            }
            #pragma unroll
            for (int fi = 0; fi < 4; fi++) {
                uint32_t a0, a1, a2, a3;
                int row = wm + fi * 16 + (lane & 15);
                int cq  = kk * 2 + (lane >> 4);
                uint32_t p = baseA + row * 64 + ((cq ^ ((row >> 1) & 3)) << 4);
                asm volatile("ldmatrix.sync.aligned.m8n8.x4.shared.b16 {%0,%1,%2,%3}, [%4];"
                             : "=r"(a0), "=r"(a1), "=r"(a2), "=r"(a3) : "r"(p));
                #pragma unroll
                for (int h = 0; h < 2; h++) {
                    asm volatile("mma.sync.aligned.m16n8k16.row.col.f32.f16.f16.f32 "
                                 "{%0,%1,%2,%3}, {%4,%5,%6,%7}, {%8,%9}, {%0,%1,%2,%3};"
                                 : "+f"(c[fi][2*h+0][0]), "+f"(c[fi][2*h+0][1]), "+f"(c[fi][2*h+0][2]), "+f"(c[fi][2*h+0][3])
                                 : "r"(a0), "r"(a1), "r"(a2), "r"(a3), "r"(bf[h][0]), "r"(bf[h][2]));
                    asm volatile("mma.sync.aligned.m16n8k16.row.col.f32.f16.f16.f32 "
                                 "{%0,%1,%2,%3}, {%4,%5,%6,%7}, {%8,%9}, {%0,%1,%2,%3};"
                                 : "+f"(c[fi][2*h+1][0]), "+f"(c[fi][2*h+1][1]), "+f"(c[fi][2*h+1][2]), "+f"(c[fi][2*h+1][3])
                                 : "r"(a0), "r"(a1), "r"(a2), "r"(a3), "r"(bf[h][1]), "r"(bf[h][3]));
                }
            }
        }
    };

    issue(0);
    if (nch > 1) issue(1);
    for (int ch = 0; ch < nch; ch++) {
        if (ch + 1 < nch) asm volatile("cp.async.wait_group 1;" ::: "memory");
        else              asm volatile("cp.async.wait_group 0;" ::: "memory");
        __syncthreads();
        if (ch + 2 < nch) issue(ch + 2);
        compute(ch % ST);
        __syncthreads();
    }

    // ---- epilogue ----
    #pragma unroll
    for (int fi = 0; fi < 4; fi++) {
        int row0 = bm + wm + fi * 16 + (lane >> 2);
        #pragma unroll
        for (int nj = 0; nj < 4; nj++) {
            int col = bn + wn + nj * 8 + (lane & 3) * 2;
            float bx = bias[col], by = bias[col + 1];
            float v0 = c[fi][nj][0] + bx, v1 = c[fi][nj][1] + by;
            float v2 = c[fi][nj][2] + bx, v3 = c[fi][nj][3] + by;
            if (OUTMODE == 1) {
                if (row0 < M)
                    *reinterpret_cast<__half2*>(&out0[(size_t)row0 * NOUT + col]) = __floats2half2_rn(v0, v1);
                if (row0 + 8 < M)
                    *reinterpret_cast<__half2*>(&out0[(size_t)(row0 + 8) * NOUT + col]) = __floats2half2_rn(v2, v3);
            } else {
                __half h0 = __float2half_rn(v0), h1 = __float2half_rn(v1);
                __half h2 = __float2half_rn(v2), h3 = __float2half_rn(v3);
                __half l0 = __float2half_rn(v0 - __half2float(h0));
                __half l1 = __float2half_rn(v1 - __half2float(h1));
                __half l2 = __float2half_rn(v2 - __half2float(h2));
                __half l3 = __float2half_rn(v3 - __half2float(h3));
                if (row0 < M) {
                    *reinterpret_cast<__half2*>(&out0[(size_t)row0 * NOUT + col]) = __halves2half2(h0, h1);
                    *reinterpret_cast<__half2*>(&out1[(size_t)row0 * NOUT + col]) = __halves2half2(l0, l1);
                }
                if (row0 + 8 < M) {
                    *reinterpret_cast<__half2*>(&out0[(size_t)(row0 + 8) * NOUT + col]) = __halves2half2(h2, h3);
                    *reinterpret_cast<__half2*>(&out1[(size_t)(row0 + 8) * NOUT + col]) = __halves2half2(l2, l3);
                }
            }
        }
    }
}

// ============================================================================
// CSR build (g_cnt zeroed by cvt_all)
// ============================================================================
__global__ void hist_kernel(const int* __restrict__ ei) {
    int e = blockIdx.x * blockDim.x + threadIdx.x;
    if (e < NEDGES) atomicAdd(&g_cnt[ei[NEDGES + e]], 1);
}

__global__ void scan_kernel() {  // 1 block, 1024 threads, warp-shuffle scan
    __shared__ int wsum[32];
    __shared__ int carry_s;
    const int t = threadIdx.x, lane = t & 31, w = t >> 5;
    if (t == 0) carry_s = 0;
    __syncthreads();
    for (int base = 0; base < NNODES; base += 1024) {
        int i = base + t;
        int v = (i < NNODES) ? g_cnt[i] : 0;
        int x = v;
        #pragma unroll
        for (int o = 1; o < 32; o <<= 1) {
            int y = __shfl_up_sync(0xffffffffu, x, o);
            if (lane >= o) x += y;
        }
        if (lane == 31) wsum[w] = x;
        __syncthreads();
        if (w == 0) {
            int s = wsum[lane];
            #pragma unroll
            for (int o = 1; o < 32; o <<= 1) {
                int y = __shfl_up_sync(0xffffffffu, s, o);
                if (lane >= o) s += y;
            }
            wsum[lane] = s;
        }
        __syncthreads();
        int incl  = x + (w > 0 ? wsum[w - 1] : 0);
        int carry = carry_s;
        if (i < NNODES) { g_rowptr[i] = carry + incl - v; g_cnt[i] = 0; }
        __syncthreads();
        if (t == 1023) carry_s = carry + incl;
        __syncthreads();
    }
    if (t == 0) g_rowptr[NNODES] = carry_s;
}

__global__ void scatter_kernel(const int* __restrict__ ei) {
    int e = blockIdx.x * blockDim.x + threadIdx.x;
    if (e < NEDGES) {
        int s = ei[e];
        int d = ei[NEDGES + e];
        int pos = g_rowptr[d] + atomicAdd(&g_cnt[d], 1);
        g_col[pos] = s;
    }
}

// ============================================================================
// Fused score + aggregate: one warp per dst node (CSR), no atomics.
// MODE 0: write relu-split hi/lo fp16. MODE 1: write fp32 (final output).
// ============================================================================
template<int MODE>
__global__ void __launch_bounds__(256) agg_kernel(
    const __half* __restrict__ AB,
    const __half* __restrict__ Hhi, const __half* __restrict__ Hlo,
    const float* __restrict__ w2, const float* __restrict__ b2,
    float* __restrict__ outf, __half* __restrict__ ohi, __half* __restrict__ olo)
{
    const int lane = threadIdx.x & 31;
    const int d    = blockIdx.x * (blockDim.x >> 5) + (threadIdx.x >> 5);
    if (d >= NNODES) return;

    const float4 w0 = *reinterpret_cast<const float4*>(&w2[lane * 8]);
    const float4 w1 = *reinterpret_cast<const float4*>(&w2[lane * 8 + 4]);
    const float  bb = b2[0];

    uint4 araw = *reinterpret_cast<const uint4*>(&AB[(size_t)d * (2 * CH) + lane * 8]);
    float2 a0 = __half22float2(*reinterpret_cast<__half2*>(&araw.x));
    float2 a1 = __half22float2(*reinterpret_cast<__half2*>(&araw.y));
    float2 a2 = __half22float2(*reinterpret_cast<__half2*>(&araw.z));
    float2 a3 = __half22float2(*reinterpret_cast<__half2*>(&araw.w));

    float acc0 = 0.f, acc1 = 0.f, acc2 = 0.f, acc3 = 0.f;
    float acc4 = 0.f, acc5 = 0.f, acc6 = 0.f, acc7 = 0.f;

    const int beg = g_rowptr[d];
    const int end = g_rowptr[d + 1];

    for (int i = beg - 1; i < end; ++i) {
        int s = (i < beg) ? d : g_col[i];

        uint4 braw = *reinterpret_cast<const uint4*>(&AB[(size_t)s * (2 * CH) + CH + lane * 8]);
        uint4 hraw = *reinterpret_cast<const uint4*>(&Hhi[(size_t)s * CH + lane * 8]);
        uint4 lraw = *reinterpret_cast<const uint4*>(&Hlo[(size_t)s * CH + lane * 8]);

        float2 b0 = __half22float2(*reinterpret_cast<__half2*>(&braw.x));
        float2 b1 = __half22float2(*reinterpret_cast<__half2*>(&braw.y));
        float2 b2v = __half22float2(*reinterpret_cast<__half2*>(&braw.z));
        float2 b3 = __half22float2(*reinterpret_cast<__half2*>(&braw.w));

        float p;
        p  = fmaxf(a0.x + b0.x, 0.f) * w0.x;
        p += fmaxf(a0.y + b0.y, 0.f) * w0.y;
        p += fmaxf(a1.x + b1.x, 0.f) * w0.z;
        p += fmaxf(a1.y + b1.y, 0.f) * w0.w;
        p += fmaxf(a2.x + b2v.x, 0.f) * w1.x;
        p += fmaxf(a2.y + b2v.y, 0.f) * w1.y;
        p += fmaxf(a3.x + b3.x, 0.f) * w1.z;
        p += fmaxf(a3.y + b3.y, 0.f) * w1.w;

        #pragma unroll
        for (int off = 16; off > 0; off >>= 1)
            p += __shfl_xor_sync(0xffffffffu, p, off);

        float score = 1.f / (1.f + __expf(-(p + bb)));

        float2 h0 = __half22float2(*reinterpret_cast<__half2*>(&hraw.x));
        float2 h1 = __half22float2(*reinterpret_cast<__half2*>(&hraw.y));
        float2 h2 = __half22float2(*reinterpret_cast<__half2*>(&hraw.z));
        float2 h3 = __half22float2(*reinterpret_cast<__half2*>(&hraw.w));
        float2 l0 = __half22float2(*reinterpret_cast<__half2*>(&lraw.x));
        float2 l1 = __half22float2(*reinterpret_cast<__half2*>(&lraw.y));
        float2 l2 = __half22float2(*reinterpret_cast<__half2*>(&lraw.z));
        float2 l3 = __half22float2(*reinterpret_cast<__half2*>(&lraw.w));

        acc0 = fmaf(score, h0.x + l0.x, acc0);
        acc1 = fmaf(score, h0.y + l0.y, acc1);
        acc2 = fmaf(score, h1.x + l1.x, acc2);
        acc3 = fmaf(score, h1.y + l1.y, acc3);
        acc4 = fmaf(score, h2.x + l2.x, acc4);
        acc5 = fmaf(score, h2.y + l2.y, acc5);
        acc6 = fmaf(score, h3.x + l3.x, acc6);
        acc7 = fmaf(score, h3.y + l3.y, acc7);
    }

    if (MODE == 1) {
        float* op = &outf[(size_t)d * CH + lane * 8];
        *reinterpret_cast<float4*>(op)     = make_float4(acc0, acc1, acc2, acc3);
        *reinterpret_cast<float4*>(op + 4) = make_float4(acc4, acc5, acc6, acc7);
    } else {
        float r[8] = {fmaxf(acc0, 0.f), fmaxf(acc1, 0.f), fmaxf(acc2, 0.f), fmaxf(acc3, 0.f),
                      fmaxf(acc4, 0.f), fmaxf(acc5, 0.f), fmaxf(acc6, 0.f), fmaxf(acc7, 0.f)};
        __half h[8], l[8];
        #pragma unroll
        for (int q = 0; q < 8; q++) {
            h[q] = __float2half_rn(r[q]);
            l[q] = __float2half_rn(r[q] - __half2float(h[q]));
        }
        uint4 hv, lv;
        hv.x = *reinterpret_cast<unsigned*>(&__halves2half2(h[0], h[1]));
        hv.y = *reinterpret_cast<unsigned*>(&__halves2half2(h[2], h[3]));
        hv.z = *reinterpret_cast<unsigned*>(&__halves2half2(h[4], h[5]));
        hv.w = *reinterpret_cast<unsigned*>(&__halves2half2(h[6], h[7]));
        lv.x = *reinterpret_cast<unsigned*>(&__halves2half2(l[0], l[1]));
        lv.y = *reinterpret_cast<unsigned*>(&__halves2half2(l[2], l[3]));
        lv.z = *reinterpret_cast<unsigned*>(&__halves2half2(l[4], l[5]));
        lv.w = *reinterpret_cast<unsigned*>(&__halves2half2(l[6], l[7]));
        *reinterpret_cast<uint4*>(&ohi[(size_t)d * CH + lane * 8]) = hv;
        *reinterpret_cast<uint4*>(&olo[(size_t)d * CH + lane * 8]) = lv;
    }
}

extern "C" void kernel_launch(void* const* d_in, const int* in_sizes, int n_in,
                              void* d_out, int out_size)
{
    (void)in_sizes; (void)n_in; (void)out_size;
    const float* x  = (const float*)d_in[0];
    const int*   ei = (const int*)d_in[1];
    const float* W_lin[3] = {(const float*)d_in[2],  (const float*)d_in[8],  (const float*)d_in[14]};
    const float* b_lin[3] = {(const float*)d_in[3],  (const float*)d_in[9],  (const float*)d_in[15]};
    const float* W_s1[3]  = {(const float*)d_in[4],  (const float*)d_in[10], (const float*)d_in[16]};
    const float* b_s1[3]  = {(const float*)d_in[5],  (const float*)d_in[11], (const float*)d_in[17]};
    const float* W_s2[3]  = {(const float*)d_in[6],  (const float*)d_in[12], (const float*)d_in[18]};
    const float* b_s2[3]  = {(const float*)d_in[7],  (const float*)d_in[13], (const float*)d_in[19]};

    __half *xhi, *xlo, *Hhi, *Hlo, *Ahi, *Alo, *AB, *Wlhi, *Wllo, *Wshi, *Wslo;
    float* bfull;
    cudaGetSymbolAddress((void**)&xhi,  g_xhi);
    cudaGetSymbolAddress((void**)&xlo,  g_xlo);
    cudaGetSymbolAddress((void**)&Hhi,  g_Hhi);
    cudaGetSymbolAddress((void**)&Hlo,  g_Hlo);
    cudaGetSymbolAddress((void**)&Ahi,  g_Ahi);
    cudaGetSymbolAddress((void**)&Alo,  g_Alo);
    cudaGetSymbolAddress((void**)&AB,   g_AB);
    cudaGetSymbolAddress((void**)&Wlhi, g_Wlhi);
    cudaGetSymbolAddress((void**)&Wllo, g_Wllo);
    cudaGetSymbolAddress((void**)&Wshi, g_Wshi);
    cudaGetSymbolAddress((void**)&Wslo, g_Wslo);
    cudaGetSymbolAddress((void**)&bfull, g_bfull);
    float* out = (float*)d_out;

    const dim3 blk(256);
    const dim3 gH((NNODES + 127) / 128, CH / 128);        // (79, 2)
    const dim3 gAB((NNODES + 127) / 128, (2 * CH) / 128); // (79, 4)
    const int  agrid = (NNODES + 7) / 8;

    // ---- fused one-shot conversions (+ cnt zeroing) ----
    cvt_all<<<(SEG_END + 255) / 256, blk>>>(x, W_lin[0], W_lin[1], W_lin[2],
                                            W_s1[0], W_s1[1], W_s1[2],
                                            b_s1[0], b_s1[1], b_s1[2]);

    // ---- CSR build (dst-keyed) ----
    hist_kernel<<<(NEDGES + 255) / 256, blk>>>(ei);
    scan_kernel<<<1, 1024>>>();
    scatter_kernel<<<(NEDGES + 255) / 256, blk>>>(ei);

    // ---- layer 1 ----
    mma_gemm<0><<<gH,  blk>>>(xhi, xlo, Wlhi, Wllo, b_lin[0], Hhi, Hlo, NNODES, 64, CH);
    mma_gemm<1><<<gAB, blk>>>(Hhi, Hlo, Wshi, Wslo, bfull, AB, AB, NNODES, CH, 2 * CH);
    agg_kernel<0><<<agrid, blk>>>(AB, Hhi, Hlo, W_s2[0], b_s2[0], nullptr, Ahi, Alo);

    // ---- layer 2 ----
    mma_gemm<0><<<gH,  blk>>>(Ahi, Alo, Wlhi + CH * CH, Wllo + CH * CH, b_lin[1], Hhi, Hlo, NNODES, CH, CH);
    mma_gemm<1><<<gAB, blk>>>(Hhi, Hlo, Wshi + 2 * CH * CH, Wslo + 2 * CH * CH, bfull + 2 * CH, AB, AB, NNODES, CH, 2 * CH);
    agg_kernel<0><<<agrid, blk>>>(AB, Hhi, Hlo, W_s2[1], b_s2[1], nullptr, Ahi, Alo);

    // ---- layer 3 (writes d_out) ----
    mma_gemm<0><<<gH,  blk>>>(Ahi, Alo, Wlhi + 2 * CH * CH, Wllo + 2 * CH * CH, b_lin[2], Hhi, Hlo, NNODES, CH, CH);
    mma_gemm<1><<<gAB, blk>>>(Hhi, Hlo, Wshi + 4 * CH * CH, Wslo + 4 * CH * CH, bfull + 4 * CH, AB, AB, NNODES, CH, 2 * CH);
    agg_kernel<1><<<agrid, blk>>>(AB, Hhi, Hlo, W_s2[2], b_s2[2], out, nullptr, nullptr);
}

// round 6
// speedup vs baseline: 1.1914x; 1.1914x over previous
#include <cuda_runtime.h>
#include <cuda_fp16.h>
#include <cstdint>

#define NNODES 10000
#define NEDGES 320000
#define CH     256

// ---- scratch (static device allocations; no cudaMalloc allowed) ----
__device__ __align__(16) __half g_xhi[NNODES * 64];
__device__ __align__(16) __half g_xlo[NNODES * 64];
__device__ __align__(16) __half g_Hhi[NNODES * CH];
__device__ __align__(16) __half g_Hlo[NNODES * CH];
__device__ __align__(16) __half g_Ahi[NNODES * CH];   // relu(agg) split, next-layer input
__device__ __align__(16) __half g_Alo[NNODES * CH];
__device__ __align__(16) __half g_AB [NNODES * 2 * CH];
__device__ __align__(16) __half g_Wlhi[3][CH * CH];
__device__ __align__(16) __half g_Wllo[3][CH * CH];
__device__ __align__(16) __half g_Wshi[3][2 * CH * CH];
__device__ __align__(16) __half g_Wslo[3][2 * CH * CH];
__device__ float g_bfull[3][2 * CH];
__device__ int g_rowptr[NNODES + 1];
__device__ int g_cnt[NNODES];
__device__ int g_col[NEDGES];

__device__ __forceinline__ uint32_t sptr(const void* p) {
    return (uint32_t)__cvta_generic_to_shared(p);
}
__device__ __forceinline__ void cpa16(uint32_t dst, const void* src, bool pred) {
    int sz = pred ? 16 : 0;
    asm volatile("cp.async.cg.shared.global [%0], [%1], 16, %2;"
                 :: "r"(dst), "l"(src), "r"(sz));
}
__device__ __forceinline__ void cpa_commit() {
    asm volatile("cp.async.commit_group;" ::: "memory");
}

// ============================================================================
// ONE fused conversion kernel: fp32 -> (hi,lo) fp16 for x, W_lin[3], W_s1[3]
// (repacked to uniform [512,256]), padded biases, and g_cnt zeroing.
// ============================================================================
#define SEG_X   (NNODES * 64)
#define SEG_E0  SEG_X
#define SEG_E1  (SEG_E0 + 16384)
#define SEG_E2  (SEG_E1 + 65536)
#define SEG_E3  (SEG_E2 + 65536)
#define SEG_E4  (SEG_E3 + 131072)
#define SEG_E5  (SEG_E4 + 131072)
#define SEG_E6  (SEG_E5 + 131072)
#define SEG_E7  (SEG_E6 + 512)
#define SEG_E8  (SEG_E7 + 512)
#define SEG_E9  (SEG_E8 + 512)
#define SEG_END (SEG_E9 + NNODES)

__global__ void __launch_bounds__(256) cvt_all(
    const float* __restrict__ x,
    const float* __restrict__ Wl1, const float* __restrict__ Wl2, const float* __restrict__ Wl3,
    const float* __restrict__ Ws1, const float* __restrict__ Ws2, const float* __restrict__ Ws3,
    const float* __restrict__ bs1, const float* __restrict__ bs2, const float* __restrict__ bs3)
{
    int i = blockIdx.x * blockDim.x + threadIdx.x;
    if (i >= SEG_END) return;
    if (i < SEG_E0) {
        float v = x[i];
        __half h = __float2half_rn(v);
        g_xhi[i] = h;
        g_xlo[i] = __float2half_rn(v - __half2float(h));
        return;
    }
    if (i < SEG_E3) {
        int l, j; const float* W;
        if (i < SEG_E1)      { l = 0; j = i - SEG_E0; W = Wl1; }
        else if (i < SEG_E2) { l = 1; j = i - SEG_E1; W = Wl2; }
        else                 { l = 2; j = i - SEG_E2; W = Wl3; }
        float v = W[j];
        __half h = __float2half_rn(v);
        g_Wlhi[l][j] = h;
        g_Wllo[l][j] = __float2half_rn(v - __half2float(h));
        return;
    }
    if (i < SEG_E6) {
        int l, j; const float* W;
        if (i < SEG_E4)      { l = 0; j = i - SEG_E3; W = Ws1; }
        else if (i < SEG_E5) { l = 1; j = i - SEG_E4; W = Ws2; }
        else                 { l = 2; j = i - SEG_E5; W = Ws3; }
        int r = j >> 8, k = j & 255;
        float v = (r < CH) ? W[r * 2 * CH + k] : W[(r - CH) * 2 * CH + CH + k];
        __half h = __float2half_rn(v);
        g_Wshi[l][j] = h;
        g_Wslo[l][j] = __float2half_rn(v - __half2float(h));
        return;
    }
    if (i < SEG_E9) {
        int l, j; const float* b;
        if (i < SEG_E7)      { l = 0; j = i - SEG_E6; b = bs1; }
        else if (i < SEG_E8) { l = 1; j = i - SEG_E7; b = bs2; }
        else                 { l = 2; j = i - SEG_E8; b = bs3; }
        g_bfull[l][j] = (j < CH) ? b[j] : 0.f;
        return;
    }
    g_cnt[i - SEG_E9] = 0;
}

// ============================================================================
// Tensor-core GEMM, split-fp16 (Markidis 3-term), pre-split operands (R4 config):
//   out = (Ahi+Alo)[M,K] @ (Whi+Wlo)[NOUT,K]^T + bias  (lo*lo dropped)
// Virtual K' = 3K over regions: (Ahi,Whi), (Alo,Whi), (Ahi,Wlo).
// BM=128 BN=64 BK=64, 8 warps, warp tile 64x16, 2-stage cp.async,
// 128B smem rows XOR-swizzled -> conflict-free ldmatrix.
// OUTMODE 0: write hi/lo fp16 split. OUTMODE 1: single fp16.
// ============================================================================
template<int OUTMODE>
__global__ void __launch_bounds__(256) mma_gemm(
    const __half* __restrict__ Ahi, const __half* __restrict__ Alo,
    const __half* __restrict__ Whi, const __half* __restrict__ Wlo,
    const float* __restrict__ bias,
    __half* __restrict__ out0, __half* __restrict__ out1,
    int M, int K, int NOUT)
{
    constexpr int BM = 128, BN = 64, BK = 64;
    __shared__ __align__(16) __half sA[2][BM * BK];   // 32 KB
    __shared__ __align__(16) __half sB[2][BN * BK];   // 16 KB

    const int tid  = threadIdx.x;
    const int lane = tid & 31;
    const int warp = tid >> 5;
    const int wm   = (warp & 1) * 64;
    const int wn   = (warp >> 1) * 16;
    const int bm   = blockIdx.x * BM;
    const int bn   = blockIdx.y * BN;
    const int nch  = (3 * K) / BK;

    const int chunk = tid & 7;       // 16B chunk within a 128B row
    const int rbase = tid >> 3;      // 0..31

    float c[4][2][4];
    #pragma unroll
    for (int i = 0; i < 4; i++)
        #pragma unroll
        for (int j = 0; j < 2; j++)
            #pragma unroll
            for (int q = 0; q < 4; q++) c[i][j][q] = 0.f;

    auto issue = [&](int ch) {
        int buf = ch & 1;
        int k0v = ch * BK;
        int region = k0v / K;
        int kreal  = k0v - region * K;
        const __half* As = (region == 1) ? Alo : Ahi;
        const __half* Ws = (region == 2) ? Wlo : Whi;
        uint32_t baseA = sptr(&sA[buf][0]);
        uint32_t baseB = sptr(&sB[buf][0]);
        #pragma unroll
        for (int i = 0; i < 4; i++) {
            int row = rbase + 32 * i;
            int gm  = bm + row;
            bool ok = gm < M;
            const __half* src = As + (size_t)(ok ? gm : 0) * K + kreal + chunk * 8;
            cpa16(baseA + row * 128 + ((chunk ^ (row & 7)) << 4), src, ok);
        }
        #pragma unroll
        for (int i = 0; i < 2; i++) {
            int row = rbase + 32 * i;
            const __half* src = Ws + (size_t)(bn + row) * K + kreal + chunk * 8;
            cpa16(baseB + row * 128 + ((chunk ^ (row & 7)) << 4), src, true);
        }
        cpa_commit();
    };

    auto compute = [&](int buf) {
        uint32_t baseA = sptr(&sA[buf][0]);
        uint32_t baseB = sptr(&sB[buf][0]);
        #pragma unroll
        for (int kk = 0; kk < 4; kk++) {
            uint32_t b0, b1, b2, b3;
            {
                int row = wn + (lane & 15);
                int cl  = kk * 2 + (lane >> 4);
                uint32_t p = baseB + row * 128 + ((cl ^ (row & 7)) << 4);
                asm volatile("ldmatrix.sync.aligned.m8n8.x4.shared.b16 {%0,%1,%2,%3}, [%4];"
                             : "=r"(b0), "=r"(b1), "=r"(b2), "=r"(b3) : "r"(p));
            }
            #pragma unroll
            for (int fi = 0; fi < 4; fi++) {
                uint32_t a0, a1, a2, a3;
                int row = wm + fi * 16 + (lane & 15);
                int cl  = kk * 2 + (lane >> 4);
                uint32_t p = baseA + row * 128 + ((cl ^ (row & 7)) << 4);
                asm volatile("ldmatrix.sync.aligned.m8n8.x4.shared.b16 {%0,%1,%2,%3}, [%4];"
                             : "=r"(a0), "=r"(a1), "=r"(a2), "=r"(a3) : "r"(p));
                asm volatile("mma.sync.aligned.m16n8k16.row.col.f32.f16.f16.f32 "
                             "{%0,%1,%2,%3}, {%4,%5,%6,%7}, {%8,%9}, {%0,%1,%2,%3};"
                             : "+f"(c[fi][0][0]), "+f"(c[fi][0][1]), "+f"(c[fi][0][2]), "+f"(c[fi][0][3])
                             : "r"(a0), "r"(a1), "r"(a2), "r"(a3), "r"(b0), "r"(b2));
                asm volatile("mma.sync.aligned.m16n8k16.row.col.f32.f16.f16.f32 "
                             "{%0,%1,%2,%3}, {%4,%5,%6,%7}, {%8,%9}, {%0,%1,%2,%3};"
                             : "+f"(c[fi][1][0]), "+f"(c[fi][1][1]), "+f"(c[fi][1][2]), "+f"(c[fi][1][3])
                             : "r"(a0), "r"(a1), "r"(a2), "r"(a3), "r"(b1), "r"(b3));
            }
        }
    };

    issue(0);
    if (nch > 1) issue(1);
    for (int ch = 0; ch < nch; ch++) {
        if (ch + 1 < nch) asm volatile("cp.async.wait_group 1;" ::: "memory");
        else              asm volatile("cp.async.wait_group 0;" ::: "memory");
        __syncthreads();
        compute(ch & 1);
        __syncthreads();
        if (ch + 2 < nch) issue(ch + 2);
    }

    // ---- epilogue ----
    #pragma unroll
    for (int fi = 0; fi < 4; fi++) {
        int row0 = bm + wm + fi * 16 + (lane >> 2);
        #pragma unroll
        for (int fj = 0; fj < 2; fj++) {
            int col = bn + wn + fj * 8 + (lane & 3) * 2;
            float bx = bias[col], by = bias[col + 1];
            float v0 = c[fi][fj][0] + bx, v1 = c[fi][fj][1] + by;
            float v2 = c[fi][fj][2] + bx, v3 = c[fi][fj][3] + by;
            if (OUTMODE == 1) {
                if (row0 < M)
                    *reinterpret_cast<__half2*>(&out0[(size_t)row0 * NOUT + col]) = __floats2half2_rn(v0, v1);
                if (row0 + 8 < M)
                    *reinterpret_cast<__half2*>(&out0[(size_t)(row0 + 8) * NOUT + col]) = __floats2half2_rn(v2, v3);
            } else {
                __half h0 = __float2half_rn(v0), h1 = __float2half_rn(v1);
                __half h2 = __float2half_rn(v2), h3 = __float2half_rn(v3);
                __half l0 = __float2half_rn(v0 - __half2float(h0));
                __half l1 = __float2half_rn(v1 - __half2float(h1));
                __half l2 = __float2half_rn(v2 - __half2float(h2));
                __half l3 = __float2half_rn(v3 - __half2float(h3));
                if (row0 < M) {
                    *reinterpret_cast<__half2*>(&out0[(size_t)row0 * NOUT + col]) = __halves2half2(h0, h1);
                    *reinterpret_cast<__half2*>(&out1[(size_t)row0 * NOUT + col]) = __halves2half2(l0, l1);
                }
                if (row0 + 8 < M) {
                    *reinterpret_cast<__half2*>(&out0[(size_t)(row0 + 8) * NOUT + col]) = __halves2half2(h2, h3);
                    *reinterpret_cast<__half2*>(&out1[(size_t)(row0 + 8) * NOUT + col]) = __halves2half2(l2, l3);
                }
            }
        }
    }
}

// ============================================================================
// CSR build (g_cnt zeroed by cvt_all)
// ============================================================================
__global__ void hist_kernel(const int* __restrict__ ei) {
    int e = blockIdx.x * blockDim.x + threadIdx.x;
    if (e < NEDGES) atomicAdd(&g_cnt[ei[NEDGES + e]], 1);
}

__global__ void scan_kernel() {  // 1 block, 1024 threads, warp-shuffle scan
    __shared__ int wsum[32];
    __shared__ int carry_s;
    const int t = threadIdx.x, lane = t & 31, w = t >> 5;
    if (t == 0) carry_s = 0;
    __syncthreads();
    for (int base = 0; base < NNODES; base += 1024) {
        int i = base + t;
        int v = (i < NNODES) ? g_cnt[i] : 0;
        int x = v;
        #pragma unroll
        for (int o = 1; o < 32; o <<= 1) {
            int y = __shfl_up_sync(0xffffffffu, x, o);
            if (lane >= o) x += y;
        }
        if (lane == 31) wsum[w] = x;
        __syncthreads();
        if (w == 0) {
            int s = wsum[lane];
            #pragma unroll
            for (int o = 1; o < 32; o <<= 1) {
                int y = __shfl_up_sync(0xffffffffu, s, o);
                if (lane >= o) s += y;
            }
            wsum[lane] = s;
        }
        __syncthreads();
        int incl  = x + (w > 0 ? wsum[w - 1] : 0);
        int carry = carry_s;
        if (i < NNODES) { g_rowptr[i] = carry + incl - v; g_cnt[i] = 0; }
        __syncthreads();
        if (t == 1023) carry_s = carry + incl;
        __syncthreads();
    }
    if (t == 0) g_rowptr[NNODES] = carry_s;
}

__global__ void scatter_kernel(const int* __restrict__ ei) {
    int e = blockIdx.x * blockDim.x + threadIdx.x;
    if (e < NEDGES) {
        int s = ei[e];
        int d = ei[NEDGES + e];
        int pos = g_rowptr[d] + atomicAdd(&g_cnt[d], 1);
        g_col[pos] = s;
    }
}

// ============================================================================
// Fused score + aggregate: one warp per dst node (CSR), no atomics.
// Messages use Hhi only (fp16): rounding noise ~2.8e-4 relative, uncorrelated
// across messages -> stays ~2.8e-4 after the sum; total rel_err ~4.5e-4 < 1e-3.
// MODE 0: write relu-split hi/lo fp16. MODE 1: write fp32 (final output).
// ============================================================================
template<int MODE>
__global__ void __launch_bounds__(256) agg_kernel(
    const __half* __restrict__ AB,
    const __half* __restrict__ Hhi,
    const float* __restrict__ w2, const float* __restrict__ b2,
    float* __restrict__ outf, __half* __restrict__ ohi, __half* __restrict__ olo)
{
    const int lane = threadIdx.x & 31;
    const int d    = blockIdx.x * (blockDim.x >> 5) + (threadIdx.x >> 5);
    if (d >= NNODES) return;

    const float4 w0 = *reinterpret_cast<const float4*>(&w2[lane * 8]);
    const float4 w1 = *reinterpret_cast<const float4*>(&w2[lane * 8 + 4]);
    const float  bb = b2[0];

    uint4 araw = *reinterpret_cast<const uint4*>(&AB[(size_t)d * (2 * CH) + lane * 8]);
    float2 a0 = __half22float2(*reinterpret_cast<__half2*>(&araw.x));
    float2 a1 = __half22float2(*reinterpret_cast<__half2*>(&araw.y));
    float2 a2 = __half22float2(*reinterpret_cast<__half2*>(&araw.z));
    float2 a3 = __half22float2(*reinterpret_cast<__half2*>(&araw.w));

    float acc0 = 0.f, acc1 = 0.f, acc2 = 0.f, acc3 = 0.f;
    float acc4 = 0.f, acc5 = 0.f, acc6 = 0.f, acc7 = 0.f;

    const int beg = g_rowptr[d];
    const int end = g_rowptr[d + 1];

    for (int i = beg - 1; i < end; ++i) {
        int s = (i < beg) ? d : g_col[i];

        uint4 braw = *reinterpret_cast<const uint4*>(&AB[(size_t)s * (2 * CH) + CH + lane * 8]);
        uint4 hraw = *reinterpret_cast<const uint4*>(&Hhi[(size_t)s * CH + lane * 8]);

        float2 b0 = __half22float2(*reinterpret_cast<__half2*>(&braw.x));
        float2 b1 = __half22float2(*reinterpret_cast<__half2*>(&braw.y));
        float2 b2v = __half22float2(*reinterpret_cast<__half2*>(&braw.z));
        float2 b3 = __half22float2(*reinterpret_cast<__half2*>(&braw.w));

        float p;
        p  = fmaxf(a0.x + b0.x, 0.f) * w0.x;
        p += fmaxf(a0.y + b0.y, 0.f) * w0.y;
        p += fmaxf(a1.x + b1.x, 0.f) * w0.z;
        p += fmaxf(a1.y + b1.y, 0.f) * w0.w;
        p += fmaxf(a2.x + b2v.x, 0.f) * w1.x;
        p += fmaxf(a2.y + b2v.y, 0.f) * w1.y;
        p += fmaxf(a3.x + b3.x, 0.f) * w1.z;
        p += fmaxf(a3.y + b3.y, 0.f) * w1.w;

        #pragma unroll
        for (int off = 16; off > 0; off >>= 1)
            p += __shfl_xor_sync(0xffffffffu, p, off);

        float score = 1.f / (1.f + __expf(-(p + bb)));

        float2 h0 = __half22float2(*reinterpret_cast<__half2*>(&hraw.x));
        float2 h1 = __half22float2(*reinterpret_cast<__half2*>(&hraw.y));
        float2 h2 = __half22float2(*reinterpret_cast<__half2*>(&hraw.z));
        float2 h3 = __half22float2(*reinterpret_cast<__half2*>(&hraw.w));

        acc0 = fmaf(score, h0.x, acc0);
        acc1 = fmaf(score, h0.y, acc1);
        acc2 = fmaf(score, h1.x, acc2);
        acc3 = fmaf(score, h1.y, acc3);
        acc4 = fmaf(score, h2.x, acc4);
        acc5 = fmaf(score, h2.y, acc5);
        acc6 = fmaf(score, h3.x, acc6);
        acc7 = fmaf(score, h3.y, acc7);
    }

    if (MODE == 1) {
        float* op = &outf[(size_t)d * CH + lane * 8];
        *reinterpret_cast<float4*>(op)     = make_float4(acc0, acc1, acc2, acc3);
        *reinterpret_cast<float4*>(op + 4) = make_float4(acc4, acc5, acc6, acc7);
    } else {
        float r[8] = {fmaxf(acc0, 0.f), fmaxf(acc1, 0.f), fmaxf(acc2, 0.f), fmaxf(acc3, 0.f),
                      fmaxf(acc4, 0.f), fmaxf(acc5, 0.f), fmaxf(acc6, 0.f), fmaxf(acc7, 0.f)};
        __half h[8], l[8];
        #pragma unroll
        for (int q = 0; q < 8; q++) {
            h[q] = __float2half_rn(r[q]);
            l[q] = __float2half_rn(r[q] - __half2float(h[q]));
        }
        uint4 hv, lv;
        hv.x = *reinterpret_cast<unsigned*>(&__halves2half2(h[0], h[1]));
        hv.y = *reinterpret_cast<unsigned*>(&__halves2half2(h[2], h[3]));
        hv.z = *reinterpret_cast<unsigned*>(&__halves2half2(h[4], h[5]));
        hv.w = *reinterpret_cast<unsigned*>(&__halves2half2(h[6], h[7]));
        lv.x = *reinterpret_cast<unsigned*>(&__halves2half2(l[0], l[1]));
        lv.y = *reinterpret_cast<unsigned*>(&__halves2half2(l[2], l[3]));
        lv.z = *reinterpret_cast<unsigned*>(&__halves2half2(l[4], l[5]));
        lv.w = *reinterpret_cast<unsigned*>(&__halves2half2(l[6], l[7]));
        *reinterpret_cast<uint4*>(&ohi[(size_t)d * CH + lane * 8]) = hv;
        *reinterpret_cast<uint4*>(&olo[(size_t)d * CH + lane * 8]) = lv;
    }
}

extern "C" void kernel_launch(void* const* d_in, const int* in_sizes, int n_in,
                              void* d_out, int out_size)
{
    (void)in_sizes; (void)n_in; (void)out_size;
    const float* x  = (const float*)d_in[0];
    const int*   ei = (const int*)d_in[1];
    const float* W_lin[3] = {(const float*)d_in[2],  (const float*)d_in[8],  (const float*)d_in[14]};
    const float* b_lin[3] = {(const float*)d_in[3],  (const float*)d_in[9],  (const float*)d_in[15]};
    const float* W_s1[3]  = {(const float*)d_in[4],  (const float*)d_in[10], (const float*)d_in[16]};
    const float* b_s1[3]  = {(const float*)d_in[5],  (const float*)d_in[11], (const float*)d_in[17]};
    const float* W_s2[3]  = {(const float*)d_in[6],  (const float*)d_in[12], (const float*)d_in[18]};
    const float* b_s2[3]  = {(const float*)d_in[7],  (const float*)d_in[13], (const float*)d_in[19]};

    __half *xhi, *xlo, *Hhi, *Hlo, *Ahi, *Alo, *AB, *Wlhi, *Wllo, *Wshi, *Wslo;
    float* bfull;
    cudaGetSymbolAddress((void**)&xhi,  g_xhi);
    cudaGetSymbolAddress((void**)&xlo,  g_xlo);
    cudaGetSymbolAddress((void**)&Hhi,  g_Hhi);
    cudaGetSymbolAddress((void**)&Hlo,  g_Hlo);
    cudaGetSymbolAddress((void**)&Ahi,  g_Ahi);
    cudaGetSymbolAddress((void**)&Alo,  g_Alo);
    cudaGetSymbolAddress((void**)&AB,   g_AB);
    cudaGetSymbolAddress((void**)&Wlhi, g_Wlhi);
    cudaGetSymbolAddress((void**)&Wllo, g_Wllo);
    cudaGetSymbolAddress((void**)&Wshi, g_Wshi);
    cudaGetSymbolAddress((void**)&Wslo, g_Wslo);
    cudaGetSymbolAddress((void**)&bfull, g_bfull);
    float* out = (float*)d_out;

    const dim3 blk(256);
    const dim3 gH((NNODES + 127) / 128, CH / 64);        // (79, 4)
    const dim3 gAB((NNODES + 127) / 128, (2 * CH) / 64); // (79, 8)
    const int  agrid = (NNODES + 7) / 8;

    // ---- fused one-shot conversions (+ cnt zeroing) ----
    cvt_all<<<(SEG_END + 255) / 256, blk>>>(x, W_lin[0], W_lin[1], W_lin[2],
                                            W_s1[0], W_s1[1], W_s1[2],
                                            b_s1[0], b_s1[1], b_s1[2]);

    // ---- CSR build (dst-keyed) ----
    hist_kernel<<<(NEDGES + 255) / 256, blk>>>(ei);
    scan_kernel<<<1, 1024>>>();
    scatter_kernel<<<(NEDGES + 255) / 256, blk>>>(ei);

    // ---- layer 1 ----
    mma_gemm<0><<<gH,  blk>>>(xhi, xlo, Wlhi, Wllo, b_lin[0], Hhi, Hlo, NNODES, 64, CH);
    mma_gemm<1><<<gAB, blk>>>(Hhi, Hlo, Wshi, Wslo, bfull, AB, AB, NNODES, CH, 2 * CH);
    agg_kernel<0><<<agrid, blk>>>(AB, Hhi, W_s2[0], b_s2[0], nullptr, Ahi, Alo);

    // ---- layer 2 ----
    mma_gemm<0><<<gH,  blk>>>(Ahi, Alo, Wlhi + CH * CH, Wllo + CH * CH, b_lin[1], Hhi, Hlo, NNODES, CH, CH);
    mma_gemm<1><<<gAB, blk>>>(Hhi, Hlo, Wshi + 2 * CH * CH, Wslo + 2 * CH * CH, bfull + 2 * CH, AB, AB, NNODES, CH, 2 * CH);
    agg_kernel<0><<<agrid, blk>>>(AB, Hhi, W_s2[1], b_s2[1], nullptr, Ahi, Alo);

    // ---- layer 3 (writes d_out) ----
    mma_gemm<0><<<gH,  blk>>>(Ahi, Alo, Wlhi + 2 * CH * CH, Wllo + 2 * CH * CH, b_lin[2], Hhi, Hlo, NNODES, CH, CH);
    mma_gemm<1><<<gAB, blk>>>(Hhi, Hlo, Wshi + 4 * CH * CH, Wslo + 4 * CH * CH, bfull + 4 * CH, AB, AB, NNODES, CH, 2 * CH);
    agg_kernel<1><<<agrid, blk>>>(AB, Hhi, W_s2[2], b_s2[2], out, nullptr, nullptr);
}

// round 7
// speedup vs baseline: 1.1988x; 1.0062x over previous
#include <cuda_runtime.h>
#include <cuda_fp16.h>
#include <cstdint>

#define NNODES 10000
#define NEDGES 320000
#define CH     256

// ---- scratch (static device allocations; no cudaMalloc allowed) ----
__device__ __align__(16) __half g_xhi[NNODES * 64];
__device__ __align__(16) __half g_xlo[NNODES * 64];
__device__ __align__(16) __half g_Hhi[NNODES * CH];
__device__ __align__(16) __half g_Ahi[NNODES * CH];   // relu(agg) split, next-layer input
__device__ __align__(16) __half g_Alo[NNODES * CH];
__device__ __align__(16) __half g_AB [NNODES * 2 * CH];
__device__ __align__(16) __half g_Wlhi[3][CH * CH];       // W_lin split (layer0: 256x64)
__device__ __align__(16) __half g_Wllo[3][CH * CH];
__device__ __align__(16) __half g_WlThi[3][CH * CH];      // W_lin^T split (rows k, cols m)
__device__ __align__(16) __half g_WlTlo[3][CH * CH];
__device__ __align__(16) __half g_Wshi[3][2 * CH * CH];   // W_s1 uniform [512,256] split
__device__ __align__(16) __half g_Wslo[3][2 * CH * CH];
__device__ __align__(16) __half g_Wchi[3][2 * CH * CH];   // Wc = Ws @ Wlin  [512, K_l] split
__device__ __align__(16) __half g_Wclo[3][2 * CH * CH];
__device__ float g_b768[3][768];                          // [b_lin | Ws@b_lin + b_s1pad]
__device__ int g_rowptr[NNODES + 1];
__device__ int g_cnt[NNODES];
__device__ int g_col[NEDGES];

__device__ __forceinline__ uint32_t sptr(const void* p) {
    return (uint32_t)__cvta_generic_to_shared(p);
}
__device__ __forceinline__ void cpa16(uint32_t dst, const void* src, bool pred) {
    int sz = pred ? 16 : 0;
    asm volatile("cp.async.cg.shared.global [%0], [%1], 16, %2;"
                 :: "r"(dst), "l"(src), "r"(sz));
}
__device__ __forceinline__ void cpa_commit() {
    asm volatile("cp.async.commit_group;" ::: "memory");
}

// ============================================================================
// ONE fused conversion kernel: x split, Wlin split, Wlin^T split, Ws uniform
// split, g_cnt zeroing.
// ============================================================================
#define CX    (NNODES * 64)
#define S_WL0 (CX)
#define S_WL1 (S_WL0 + 16384)
#define S_WL2 (S_WL1 + 65536)
#define S_WT0 (S_WL2 + 65536)
#define S_WT1 (S_WT0 + 16384)
#define S_WT2 (S_WT1 + 65536)
#define S_WS0 (S_WT2 + 65536)
#define S_WS1 (S_WS0 + 131072)
#define S_WS2 (S_WS1 + 131072)
#define S_CNT (S_WS2 + 131072)
#define S_END (S_CNT + NNODES)

__global__ void __launch_bounds__(256) cvt_all(
    const float* __restrict__ x,
    const float* __restrict__ Wl1, const float* __restrict__ Wl2, const float* __restrict__ Wl3,
    const float* __restrict__ Ws1, const float* __restrict__ Ws2, const float* __restrict__ Ws3)
{
    int i = blockIdx.x * blockDim.x + threadIdx.x;
    if (i >= S_END) return;
    if (i < CX) {
        float v = x[i];
        __half h = __float2half_rn(v);
        g_xhi[i] = h;
        g_xlo[i] = __float2half_rn(v - __half2float(h));
        return;
    }
    if (i < S_WT0) {   // Wlin linear copy+split
        int l, j; const float* W;
        if (i < S_WL1)      { l = 0; j = i - S_WL0; W = Wl1; }
        else if (i < S_WL2) { l = 1; j = i - S_WL1; W = Wl2; }
        else                { l = 2; j = i - S_WL2; W = Wl3; }
        float v = W[j];
        __half h = __float2half_rn(v);
        g_Wlhi[l][j] = h;
        g_Wllo[l][j] = __float2half_rn(v - __half2float(h));
        return;
    }
    if (i < S_WS0) {   // Wlin^T: row k (out col), col m; src Wlin[m*Kin + k]
        int l, j, kin; const float* W;
        if (i < S_WT1)      { l = 0; j = i - S_WT0; W = Wl1; kin = 64; }
        else if (i < S_WT2) { l = 1; j = i - S_WT1; W = Wl2; kin = 256; }
        else                { l = 2; j = i - S_WT2; W = Wl3; kin = 256; }
        int k = j >> 8, m = j & 255;
        float v = W[m * kin + k];
        __half h = __float2half_rn(v);
        g_WlThi[l][j] = h;
        g_WlTlo[l][j] = __float2half_rn(v - __half2float(h));
        return;
    }
    if (i < S_CNT) {   // Ws uniform repack + split
        int l, j; const float* W;
        if (i < S_WS1)      { l = 0; j = i - S_WS0; W = Ws1; }
        else if (i < S_WS2) { l = 1; j = i - S_WS1; W = Ws2; }
        else                { l = 2; j = i - S_WS2; W = Ws3; }
        int r = j >> 8, k = j & 255;
        float v = (r < CH) ? W[r * 2 * CH + k] : W[(r - CH) * 2 * CH + CH + k];
        __half h = __float2half_rn(v);
        g_Wshi[l][j] = h;
        g_Wslo[l][j] = __float2half_rn(v - __half2float(h));
        return;
    }
    g_cnt[i - S_CNT] = 0;
}

// ============================================================================
// Fused bias: b768[l] = [b_lin | Ws_uniform @ b_lin + b_s1_padded]
// ============================================================================
__global__ void __launch_bounds__(256) bias_kernel(
    const float* __restrict__ bl1, const float* __restrict__ bl2, const float* __restrict__ bl3,
    const float* __restrict__ Ws1, const float* __restrict__ Ws2, const float* __restrict__ Ws3,
    const float* __restrict__ bs1, const float* __restrict__ bs2, const float* __restrict__ bs3)
{
    int i = blockIdx.x * blockDim.x + threadIdx.x;
    if (i >= 3 * 768) return;
    int l = i / 768, j = i % 768;
    const float* bl = (l == 0) ? bl1 : (l == 1) ? bl2 : bl3;
    const float* Ws = (l == 0) ? Ws1 : (l == 1) ? Ws2 : Ws3;
    const float* bs = (l == 0) ? bs1 : (l == 1) ? bs2 : bs3;
    if (j < 256) { g_b768[l][j] = bl[j]; return; }
    int r = j - 256;
    float acc = (r < CH) ? bs[r] : 0.f;
    for (int m = 0; m < 256; m++) {
        float w = (r < CH) ? Ws[r * 2 * CH + m] : Ws[(r - CH) * 2 * CH + CH + m];
        acc += w * bl[m];
    }
    g_b768[l][j] = acc;
}

// ============================================================================
// GEMM core: split-fp16 (Markidis 3-term), pre-split operands.
// Virtual K' = 3K over regions: (Ahi,W hi), (Alo,W hi), (Ahi,W lo).
// BM=128 BN=64 BK=64, 8 warps, 2-stage cp.async, 128B-row XOR swizzle.
// DUALW: weight rows n<256 from Wa (stride K), n>=256 from Wb (stride K).
// OUTMODE 0: hi/lo split to out0/out1 (row stride = ostride).
// OUTMODE 1: single fp16; n<256 -> out0 stride 256, n>=256 -> out1 stride 512.
// ============================================================================
template<int OUTMODE, bool DUALW>
__device__ __forceinline__ void gemm_core(
    const __half* __restrict__ Ahi, const __half* __restrict__ Alo,
    const __half* __restrict__ Wahi, const __half* __restrict__ Walo,
    const __half* __restrict__ Wbhi, const __half* __restrict__ Wblo,
    const float* __restrict__ bias,
    __half* __restrict__ out0, __half* __restrict__ out1,
    int M, int K, int ostride, int bm, int bn)
{
    constexpr int BM = 128, BN = 64, BK = 64;
    __shared__ __align__(16) __half sA[2][BM * BK];   // 32 KB
    __shared__ __align__(16) __half sB[2][BN * BK];   // 16 KB

    const int tid  = threadIdx.x;
    const int lane = tid & 31;
    const int warp = tid >> 5;
    const int wm   = (warp & 1) * 64;
    const int wn   = (warp >> 1) * 16;
    const int nch  = (3 * K) / BK;

    const int chunk = tid & 7;
    const int rbase = tid >> 3;

    const bool useB = DUALW && (bn >= 256);
    const int  nb   = useB ? bn - 256 : bn;
    const __half* Whi = useB ? Wbhi : Wahi;
    const __half* Wlo = useB ? Wblo : Walo;

    float c[4][2][4];
    #pragma unroll
    for (int i = 0; i < 4; i++)
        #pragma unroll
        for (int j = 0; j < 2; j++)
            #pragma unroll
            for (int q = 0; q < 4; q++) c[i][j][q] = 0.f;

    auto issue = [&](int ch) {
        int buf = ch & 1;
        int k0v = ch * BK;
        int region = k0v / K;
        int kreal  = k0v - region * K;
        const __half* As = (region == 1) ? Alo : Ahi;
        const __half* Ws = (region == 2) ? Wlo : Whi;
        uint32_t baseA = sptr(&sA[buf][0]);
        uint32_t baseB = sptr(&sB[buf][0]);
        #pragma unroll
        for (int i = 0; i < 4; i++) {
            int row = rbase + 32 * i;
            int gm  = bm + row;
            bool ok = gm < M;
            const __half* src = As + (size_t)(ok ? gm : 0) * K + kreal + chunk * 8;
            cpa16(baseA + row * 128 + ((chunk ^ (row & 7)) << 4), src, ok);
        }
        #pragma unroll
        for (int i = 0; i < 2; i++) {
            int row = rbase + 32 * i;
            const __half* src = Ws + (size_t)(nb + row) * K + kreal + chunk * 8;
            cpa16(baseB + row * 128 + ((chunk ^ (row & 7)) << 4), src, true);
        }
        cpa_commit();
    };

    auto compute = [&](int buf) {
        uint32_t baseA = sptr(&sA[buf][0]);
        uint32_t baseB = sptr(&sB[buf][0]);
        #pragma unroll
        for (int kk = 0; kk < 4; kk++) {
            uint32_t b0, b1, b2, b3;
            {
                int row = wn + (lane & 15);
                int cl  = kk * 2 + (lane >> 4);
                uint32_t p = baseB + row * 128 + ((cl ^ (row & 7)) << 4);
                asm volatile("ldmatrix.sync.aligned.m8n8.x4.shared.b16 {%0,%1,%2,%3}, [%4];"
                             : "=r"(b0), "=r"(b1), "=r"(b2), "=r"(b3) : "r"(p));
            }
            #pragma unroll
            for (int fi = 0; fi < 4; fi++) {
                uint32_t a0, a1, a2, a3;
                int row = wm + fi * 16 + (lane & 15);
                int cl  = kk * 2 + (lane >> 4);
                uint32_t p = baseA + row * 128 + ((cl ^ (row & 7)) << 4);
                asm volatile("ldmatrix.sync.aligned.m8n8.x4.shared.b16 {%0,%1,%2,%3}, [%4];"
                             : "=r"(a0), "=r"(a1), "=r"(a2), "=r"(a3) : "r"(p));
                asm volatile("mma.sync.aligned.m16n8k16.row.col.f32.f16.f16.f32 "
                             "{%0,%1,%2,%3}, {%4,%5,%6,%7}, {%8,%9}, {%0,%1,%2,%3};"
                             : "+f"(c[fi][0][0]), "+f"(c[fi][0][1]), "+f"(c[fi][0][2]), "+f"(c[fi][0][3])
                             : "r"(a0), "r"(a1), "r"(a2), "r"(a3), "r"(b0), "r"(b2));
                asm volatile("mma.sync.aligned.m16n8k16.row.col.f32.f16.f16.f32 "
                             "{%0,%1,%2,%3}, {%4,%5,%6,%7}, {%8,%9}, {%0,%1,%2,%3};"
                             : "+f"(c[fi][1][0]), "+f"(c[fi][1][1]), "+f"(c[fi][1][2]), "+f"(c[fi][1][3])
                             : "r"(a0), "r"(a1), "r"(a2), "r"(a3), "r"(b1), "r"(b3));
            }
        }
    };

    issue(0);
    if (nch > 1) issue(1);
    for (int ch = 0; ch < nch; ch++) {
        if (ch + 1 < nch) asm volatile("cp.async.wait_group 1;" ::: "memory");
        else              asm volatile("cp.async.wait_group 0;" ::: "memory");
        __syncthreads();
        compute(ch & 1);
        __syncthreads();
        if (ch + 2 < nch) issue(ch + 2);
    }

    // ---- epilogue ----
    __half* dst;
    int stride, cb;
    if (OUTMODE == 1) {
        dst    = useB ? out1 : out0;
        stride = useB ? 512 : 256;
        cb     = nb;
    } else {
        dst    = out0;
        stride = ostride;
        cb     = bn;
    }
    #pragma unroll
    for (int fi = 0; fi < 4; fi++) {
        int row0 = bm + wm + fi * 16 + (lane >> 2);
        #pragma unroll
        for (int fj = 0; fj < 2; fj++) {
            int cl = wn + fj * 8 + (lane & 3) * 2;
            float bx = 0.f, by = 0.f;
            if (OUTMODE == 1) { bx = bias[bn + cl]; by = bias[bn + cl + 1]; }
            float v0 = c[fi][fj][0] + bx, v1 = c[fi][fj][1] + by;
            float v2 = c[fi][fj][2] + bx, v3 = c[fi][fj][3] + by;
            int col = cb + cl;
            if (OUTMODE == 1) {
                if (row0 < M)
                    *reinterpret_cast<__half2*>(&dst[(size_t)row0 * stride + col]) = __floats2half2_rn(v0, v1);
                if (row0 + 8 < M)
                    *reinterpret_cast<__half2*>(&dst[(size_t)(row0 + 8) * stride + col]) = __floats2half2_rn(v2, v3);
            } else {
                __half h0 = __float2half_rn(v0), h1 = __float2half_rn(v1);
                __half h2 = __float2half_rn(v2), h3 = __float2half_rn(v3);
                __half l0 = __float2half_rn(v0 - __half2float(h0));
                __half l1 = __float2half_rn(v1 - __half2float(h1));
                __half l2 = __float2half_rn(v2 - __half2float(h2));
                __half l3 = __float2half_rn(v3 - __half2float(h3));
                if (row0 < M) {
                    *reinterpret_cast<__half2*>(&out0[(size_t)row0 * stride + col]) = __halves2half2(h0, h1);
                    *reinterpret_cast<__half2*>(&out1[(size_t)row0 * stride + col]) = __halves2half2(l0, l1);
                }
                if (row0 + 8 < M) {
                    *reinterpret_cast<__half2*>(&out0[(size_t)(row0 + 8) * stride + col]) = __halves2half2(h2, h3);
                    *reinterpret_cast<__half2*>(&out1[(size_t)(row0 + 8) * stride + col]) = __halves2half2(l2, l3);
                }
            }
        }
    }
}

// Batched Wc precompute: Wc[l] = Ws_uniform[l] @ Wlin[l]  ([512, K_l], split out)
// grid (4, 4, 3); layer 0 has K_in=64 -> blocks with bn>=64 exit.
__global__ void __launch_bounds__(256) wc_gemm() {
    int l  = blockIdx.z;
    int bn = blockIdx.y * 64;
    int nout = (l == 0) ? 64 : 256;
    if (bn >= nout) return;
    gemm_core<0, false>(g_Wshi[l], g_Wslo[l], g_WlThi[l], g_WlTlo[l],
                        nullptr, nullptr, nullptr,
                        g_Wchi[l], g_Wclo[l], 512, 256, nout,
                        blockIdx.x * 128, bn);
}

// Fused per-layer GEMM: [Hhi | AB] = relu_in @ [Wlin ; Wc]^T + b768
__global__ void __launch_bounds__(256) layer_gemm(
    const __half* __restrict__ Ahi, const __half* __restrict__ Alo,
    int l, int K, __half* __restrict__ Hhi, __half* __restrict__ AB)
{
    gemm_core<1, true>(Ahi, Alo, g_Wlhi[l], g_Wllo[l], g_Wchi[l], g_Wclo[l],
                       g_b768[l], Hhi, AB, NNODES, K, 0,
                       blockIdx.x * 128, blockIdx.y * 64);
}

// ============================================================================
// CSR build (g_cnt zeroed by cvt_all)
// ============================================================================
__global__ void hist_kernel(const int* __restrict__ ei) {
    int e = blockIdx.x * blockDim.x + threadIdx.x;
    if (e < NEDGES) atomicAdd(&g_cnt[ei[NEDGES + e]], 1);
}

__global__ void scan_kernel() {  // 1 block, 1024 threads, warp-shuffle scan
    __shared__ int wsum[32];
    __shared__ int carry_s;
    const int t = threadIdx.x, lane = t & 31, w = t >> 5;
    if (t == 0) carry_s = 0;
    __syncthreads();
    for (int base = 0; base < NNODES; base += 1024) {
        int i = base + t;
        int v = (i < NNODES) ? g_cnt[i] : 0;
        int x = v;
        #pragma unroll
        for (int o = 1; o < 32; o <<= 1) {
            int y = __shfl_up_sync(0xffffffffu, x, o);
            if (lane >= o) x += y;
        }
        if (lane == 31) wsum[w] = x;
        __syncthreads();
        if (w == 0) {
            int s = wsum[lane];
            #pragma unroll
            for (int o = 1; o < 32; o <<= 1) {
                int y = __shfl_up_sync(0xffffffffu, s, o);
                if (lane >= o) s += y;
            }
            wsum[lane] = s;
        }
        __syncthreads();
        int incl  = x + (w > 0 ? wsum[w - 1] : 0);
        int carry = carry_s;
        if (i < NNODES) { g_rowptr[i] = carry + incl - v; g_cnt[i] = 0; }
        __syncthreads();
        if (t == 1023) carry_s = carry + incl;
        __syncthreads();
    }
    if (t == 0) g_rowptr[NNODES] = carry_s;
}

__global__ void scatter_kernel(const int* __restrict__ ei) {
    int e = blockIdx.x * blockDim.x + threadIdx.x;
    if (e < NEDGES) {
        int s = ei[e];
        int d = ei[NEDGES + e];
        int pos = g_rowptr[d] + atomicAdd(&g_cnt[d], 1);
        g_col[pos] = s;
    }
}

// ============================================================================
// Fused score + aggregate: one warp per dst node (CSR), no atomics.
// MODE 0: write relu-split hi/lo fp16. MODE 1: write fp32 (final output).
// ============================================================================
template<int MODE>
__global__ void __launch_bounds__(256) agg_kernel(
    const __half* __restrict__ AB,
    const __half* __restrict__ Hhi,
    const float* __restrict__ w2, const float* __restrict__ b2,
    float* __restrict__ outf, __half* __restrict__ ohi, __half* __restrict__ olo)
{
    const int lane = threadIdx.x & 31;
    const int d    = blockIdx.x * (blockDim.x >> 5) + (threadIdx.x >> 5);
    if (d >= NNODES) return;

    const float4 w0 = *reinterpret_cast<const float4*>(&w2[lane * 8]);
    const float4 w1 = *reinterpret_cast<const float4*>(&w2[lane * 8 + 4]);
    const float  bb = b2[0];

    uint4 araw = *reinterpret_cast<const uint4*>(&AB[(size_t)d * (2 * CH) + lane * 8]);
    float2 a0 = __half22float2(*reinterpret_cast<__half2*>(&araw.x));
    float2 a1 = __half22float2(*reinterpret_cast<__half2*>(&araw.y));
    float2 a2 = __half22float2(*reinterpret_cast<__half2*>(&araw.z));
    float2 a3 = __half22float2(*reinterpret_cast<__half2*>(&araw.w));

    float acc0 = 0.f, acc1 = 0.f, acc2 = 0.f, acc3 = 0.f;
    float acc4 = 0.f, acc5 = 0.f, acc6 = 0.f, acc7 = 0.f;

    const int beg = g_rowptr[d];
    const int end = g_rowptr[d + 1];

    for (int i = beg - 1; i < end; ++i) {
        int s = (i < beg) ? d : g_col[i];

        uint4 braw = *reinterpret_cast<const uint4*>(&AB[(size_t)s * (2 * CH) + CH + lane * 8]);
        uint4 hraw = *reinterpret_cast<const uint4*>(&Hhi[(size_t)s * CH + lane * 8]);

        float2 b0 = __half22float2(*reinterpret_cast<__half2*>(&braw.x));
        float2 b1 = __half22float2(*reinterpret_cast<__half2*>(&braw.y));
        float2 b2v = __half22float2(*reinterpret_cast<__half2*>(&braw.z));
        float2 b3 = __half22float2(*reinterpret_cast<__half2*>(&braw.w));

        float p;
        p  = fmaxf(a0.x + b0.x, 0.f) * w0.x;
        p += fmaxf(a0.y + b0.y, 0.f) * w0.y;
        p += fmaxf(a1.x + b1.x, 0.f) * w0.z;
        p += fmaxf(a1.y + b1.y, 0.f) * w0.w;
        p += fmaxf(a2.x + b2v.x, 0.f) * w1.x;
        p += fmaxf(a2.y + b2v.y, 0.f) * w1.y;
        p += fmaxf(a3.x + b3.x, 0.f) * w1.z;
        p += fmaxf(a3.y + b3.y, 0.f) * w1.w;

        #pragma unroll
        for (int off = 16; off > 0; off >>= 1)
            p += __shfl_xor_sync(0xffffffffu, p, off);

        float score = 1.f / (1.f + __expf(-(p + bb)));

        float2 h0 = __half22float2(*reinterpret_cast<__half2*>(&hraw.x));
        float2 h1 = __half22float2(*reinterpret_cast<__half2*>(&hraw.y));
        float2 h2 = __half22float2(*reinterpret_cast<__half2*>(&hraw.z));
        float2 h3 = __half22float2(*reinterpret_cast<__half2*>(&hraw.w));

        acc0 = fmaf(score, h0.x, acc0);
        acc1 = fmaf(score, h0.y, acc1);
        acc2 = fmaf(score, h1.x, acc2);
        acc3 = fmaf(score, h1.y, acc3);
        acc4 = fmaf(score, h2.x, acc4);
        acc5 = fmaf(score, h2.y, acc5);
        acc6 = fmaf(score, h3.x, acc6);
        acc7 = fmaf(score, h3.y, acc7);
    }

    if (MODE == 1) {
        float* op = &outf[(size_t)d * CH + lane * 8];
        *reinterpret_cast<float4*>(op)     = make_float4(acc0, acc1, acc2, acc3);
        *reinterpret_cast<float4*>(op + 4) = make_float4(acc4, acc5, acc6, acc7);
    } else {
        float r[8] = {fmaxf(acc0, 0.f), fmaxf(acc1, 0.f), fmaxf(acc2, 0.f), fmaxf(acc3, 0.f),
                      fmaxf(acc4, 0.f), fmaxf(acc5, 0.f), fmaxf(acc6, 0.f), fmaxf(acc7, 0.f)};
        __half h[8], l[8];
        #pragma unroll
        for (int q = 0; q < 8; q++) {
            h[q] = __float2half_rn(r[q]);
            l[q] = __float2half_rn(r[q] - __half2float(h[q]));
        }
        uint4 hv, lv;
        hv.x = *reinterpret_cast<unsigned*>(&__halves2half2(h[0], h[1]));
        hv.y = *reinterpret_cast<unsigned*>(&__halves2half2(h[2], h[3]));
        hv.z = *reinterpret_cast<unsigned*>(&__halves2half2(h[4], h[5]));
        hv.w = *reinterpret_cast<unsigned*>(&__halves2half2(h[6], h[7]));
        lv.x = *reinterpret_cast<unsigned*>(&__halves2half2(l[0], l[1]));
        lv.y = *reinterpret_cast<unsigned*>(&__halves2half2(l[2], l[3]));
        lv.z = *reinterpret_cast<unsigned*>(&__halves2half2(l[4], l[5]));
        lv.w = *reinterpret_cast<unsigned*>(&__halves2half2(l[6], l[7]));
        *reinterpret_cast<uint4*>(&ohi[(size_t)d * CH + lane * 8]) = hv;
        *reinterpret_cast<uint4*>(&olo[(size_t)d * CH + lane * 8]) = lv;
    }
}

extern "C" void kernel_launch(void* const* d_in, const int* in_sizes, int n_in,
                              void* d_out, int out_size)
{
    (void)in_sizes; (void)n_in; (void)out_size;
    const float* x  = (const float*)d_in[0];
    const int*   ei = (const int*)d_in[1];
    const float* W_lin[3] = {(const float*)d_in[2],  (const float*)d_in[8],  (const float*)d_in[14]};
    const float* b_lin[3] = {(const float*)d_in[3],  (const float*)d_in[9],  (const float*)d_in[15]};
    const float* W_s1[3]  = {(const float*)d_in[4],  (const float*)d_in[10], (const float*)d_in[16]};
    const float* b_s1[3]  = {(const float*)d_in[5],  (const float*)d_in[11], (const float*)d_in[17]};
    const float* W_s2[3]  = {(const float*)d_in[6],  (const float*)d_in[12], (const float*)d_in[18]};
    const float* b_s2[3]  = {(const float*)d_in[7],  (const float*)d_in[13], (const float*)d_in[19]};

    __half *xhi, *xlo, *Hhi, *Ahi, *Alo, *AB;
    cudaGetSymbolAddress((void**)&xhi, g_xhi);
    cudaGetSymbolAddress((void**)&xlo, g_xlo);
    cudaGetSymbolAddress((void**)&Hhi, g_Hhi);
    cudaGetSymbolAddress((void**)&Ahi, g_Ahi);
    cudaGetSymbolAddress((void**)&Alo, g_Alo);
    cudaGetSymbolAddress((void**)&AB,  g_AB);
    float* out = (float*)d_out;

    const dim3 blk(256);
    const dim3 gL((NNODES + 127) / 128, 768 / 64);   // (79, 12)
    const dim3 gWc(4, 4, 3);
    const int  agrid = (NNODES + 7) / 8;

    // ---- one-shot weight prep ----
    cvt_all<<<(S_END + 255) / 256, blk>>>(x, W_lin[0], W_lin[1], W_lin[2],
                                          W_s1[0], W_s1[1], W_s1[2]);
    bias_kernel<<<(3 * 768 + 255) / 256, blk>>>(b_lin[0], b_lin[1], b_lin[2],
                                                W_s1[0], W_s1[1], W_s1[2],
                                                b_s1[0], b_s1[1], b_s1[2]);
    wc_gemm<<<gWc, blk>>>();

    // ---- CSR build (dst-keyed) ----
    hist_kernel<<<(NEDGES + 255) / 256, blk>>>(ei);
    scan_kernel<<<1, 1024>>>();
    scatter_kernel<<<(NEDGES + 255) / 256, blk>>>(ei);

    // ---- layer 1 ----
    layer_gemm<<<gL, blk>>>(xhi, xlo, 0, 64, Hhi, AB);
    agg_kernel<0><<<agrid, blk>>>(AB, Hhi, W_s2[0], b_s2[0], nullptr, Ahi, Alo);

    // ---- layer 2 ----
    layer_gemm<<<gL, blk>>>(Ahi, Alo, 1, 256, Hhi, AB);
    agg_kernel<0><<<agrid, blk>>>(AB, Hhi, W_s2[1], b_s2[1], nullptr, Ahi, Alo);

    // ---- layer 3 (writes d_out) ----
    layer_gemm<<<gL, blk>>>(Ahi, Alo, 2, 256, Hhi, AB);
    agg_kernel<1><<<agrid, blk>>>(AB, Hhi, W_s2[2], b_s2[2], out, nullptr, nullptr);
}

// round 8
// speedup vs baseline: 1.3176x; 1.0991x over previous
#include <cuda_runtime.h>
#include <cuda_fp16.h>
#include <cstdint>

#define NNODES 10000
#define NEDGES 320000
#define CH     256

// ---- scratch (static device allocations; no cudaMalloc allowed) ----
__device__ __align__(16) __half g_xhi[NNODES * 64];
__device__ __align__(16) __half g_xlo[NNODES * 64];
__device__ __align__(16) __half g_Hhi[NNODES * CH];
__device__ __align__(16) __half g_Ahi[NNODES * CH];   // relu(agg) split, next-layer input
__device__ __align__(16) __half g_Alo[NNODES * CH];
__device__ __align__(16) __half g_AB [NNODES * 2 * CH];
__device__ __align__(16) __half g_Wlhi[3][CH * CH];       // W_lin fp16 (layer0: 256x64)
__device__ __align__(16) __half g_WlThi[3][CH * CH];      // W_lin^T fp16 (rows k_in, cols m)
__device__ __align__(16) __half g_Wshi[3][2 * CH * CH];   // W_s1 uniform [512,256] split
__device__ __align__(16) __half g_Wslo[3][2 * CH * CH];
__device__ __align__(16) __half g_Wchi[3][2 * CH * CH];   // Wc = Ws @ Wlin  [512, K_l] fp16
__device__ float g_b768[3][768];                          // [b_lin | Ws@b_lin + b_s1pad]
__device__ int g_rowptr[NNODES + 1];
__device__ int g_cnt[NNODES];
__device__ int g_col[NEDGES];

__device__ __forceinline__ uint32_t sptr(const void* p) {
    return (uint32_t)__cvta_generic_to_shared(p);
}
__device__ __forceinline__ void cpa16(uint32_t dst, const void* src, bool pred) {
    int sz = pred ? 16 : 0;
    asm volatile("cp.async.cg.shared.global [%0], [%1], 16, %2;"
                 :: "r"(dst), "l"(src), "r"(sz));
}
__device__ __forceinline__ void cpa_commit() {
    asm volatile("cp.async.commit_group;" ::: "memory");
}

// ============================================================================
// ONE fused conversion kernel: x split, Wlin fp16, Wlin^T fp16, Ws uniform
// split (hi+lo, for accurate Wc), g_cnt zeroing.
// ============================================================================
#define CX    (NNODES * 64)
#define S_WL0 (CX)
#define S_WL1 (S_WL0 + 16384)
#define S_WL2 (S_WL1 + 65536)
#define S_WT0 (S_WL2 + 65536)
#define S_WT1 (S_WT0 + 16384)
#define S_WT2 (S_WT1 + 65536)
#define S_WS0 (S_WT2 + 65536)
#define S_WS1 (S_WS0 + 131072)
#define S_WS2 (S_WS1 + 131072)
#define S_CNT (S_WS2 + 131072)
#define S_END (S_CNT + NNODES)

__global__ void __launch_bounds__(256) cvt_all(
    const float* __restrict__ x,
    const float* __restrict__ Wl1, const float* __restrict__ Wl2, const float* __restrict__ Wl3,
    const float* __restrict__ Ws1, const float* __restrict__ Ws2, const float* __restrict__ Ws3)
{
    int i = blockIdx.x * blockDim.x + threadIdx.x;
    if (i >= S_END) return;
    if (i < CX) {
        float v = x[i];
        __half h = __float2half_rn(v);
        g_xhi[i] = h;
        g_xlo[i] = __float2half_rn(v - __half2float(h));
        return;
    }
    if (i < S_WT0) {   // Wlin fp16 copy
        int l, j; const float* W;
        if (i < S_WL1)      { l = 0; j = i - S_WL0; W = Wl1; }
        else if (i < S_WL2) { l = 1; j = i - S_WL1; W = Wl2; }
        else                { l = 2; j = i - S_WL2; W = Wl3; }
        g_Wlhi[l][j] = __float2half_rn(W[j]);
        return;
    }
    if (i < S_WS0) {   // Wlin^T fp16: [k_in][m] from Wlin[m*kin + k]
        int l, j, kin; const float* W;
        if (i < S_WT1)      { l = 0; j = i - S_WT0; W = Wl1; kin = 64; }
        else if (i < S_WT2) { l = 1; j = i - S_WT1; W = Wl2; kin = 256; }
        else                { l = 2; j = i - S_WT2; W = Wl3; kin = 256; }
        int k = j >> 8, m = j & 255;
        g_WlThi[l][j] = __float2half_rn(W[m * kin + k]);
        return;
    }
    if (i < S_CNT) {   // Ws uniform repack + hi/lo split
        int l, j; const float* W;
        if (i < S_WS1)      { l = 0; j = i - S_WS0; W = Ws1; }
        else if (i < S_WS2) { l = 1; j = i - S_WS1; W = Ws2; }
        else                { l = 2; j = i - S_WS2; W = Ws3; }
        int r = j >> 8, k = j & 255;
        float v = (r < CH) ? W[r * 2 * CH + k] : W[(r - CH) * 2 * CH + CH + k];
        __half h = __float2half_rn(v);
        g_Wshi[l][j] = h;
        g_Wslo[l][j] = __float2half_rn(v - __half2float(h));
        return;
    }
    g_cnt[i - S_CNT] = 0;
}

// ============================================================================
// Fused bias: b768[l] = [b_lin | Ws_uniform @ b_lin + b_s1_padded]
// ============================================================================
__global__ void __launch_bounds__(256) bias_kernel(
    const float* __restrict__ bl1, const float* __restrict__ bl2, const float* __restrict__ bl3,
    const float* __restrict__ Ws1, const float* __restrict__ Ws2, const float* __restrict__ Ws3,
    const float* __restrict__ bs1, const float* __restrict__ bs2, const float* __restrict__ bs3)
{
    int i = blockIdx.x * blockDim.x + threadIdx.x;
    if (i >= 3 * 768) return;
    int l = i / 768, j = i % 768;
    const float* bl = (l == 0) ? bl1 : (l == 1) ? bl2 : bl3;
    const float* Ws = (l == 0) ? Ws1 : (l == 1) ? Ws2 : Ws3;
    const float* bs = (l == 0) ? bs1 : (l == 1) ? bs2 : bs3;
    if (j < 256) { g_b768[l][j] = bl[j]; return; }
    int r = j - 256;
    float acc = (r < CH) ? bs[r] : 0.f;
    for (int m = 0; m < 256; m++) {
        float w = (r < CH) ? Ws[r * 2 * CH + m] : Ws[(r - CH) * 2 * CH + CH + m];
        acc += w * bl[m];
    }
    g_b768[l][j] = acc;
}

// ============================================================================
// GEMM core: 2-region split (A = hi+lo exact vs fp16 W; W fp16 single).
// Virtual K' = 2K over regions: (Ahi,W), (Alo,W).
// BM=128 BN=64 BK=64, 8 warps, warp tile 32x32 (4M x 2N), 2-stage cp.async,
// 128B-row XOR swizzle. Per k16 step: 4 LDSM feed 8 MMAs.
// DUALW: weight rows n<256 from Wa, n>=256 from Wb (both stride K).
// OUTMODE 1: dual single-fp16 out (n<256 -> out0 stride 256, else out1 stride 512), +bias.
// OUTMODE 2: single fp16 out0 stride ostride, no bias.
// ============================================================================
template<int OUTMODE, bool DUALW>
__device__ __forceinline__ void gemm_core(
    const __half* __restrict__ Ahi, const __half* __restrict__ Alo,
    const __half* __restrict__ Wahi, const __half* __restrict__ Wbhi,
    const float* __restrict__ bias,
    __half* __restrict__ out0, __half* __restrict__ out1,
    int M, int K, int ostride, int bm, int bn)
{
    constexpr int BM = 128, BN = 64, BK = 64;
    __shared__ __align__(16) __half sA[2][BM * BK];   // 32 KB
    __shared__ __align__(16) __half sB[2][BN * BK];   // 16 KB

    const int tid  = threadIdx.x;
    const int lane = tid & 31;
    const int warp = tid >> 5;
    const int wm   = (warp >> 1) * 32;   // 4 M-groups
    const int wn   = (warp & 1) * 32;    // 2 N-groups
    const int nch  = (2 * K) / BK;

    const int chunk = tid & 7;
    const int rbase = tid >> 3;

    const bool useB = DUALW && (bn >= 256);
    const int  nb   = useB ? bn - 256 : bn;
    const __half* Whi = useB ? Wbhi : Wahi;

    float c[2][4][4];
    #pragma unroll
    for (int i = 0; i < 2; i++)
        #pragma unroll
        for (int j = 0; j < 4; j++)
            #pragma unroll
            for (int q = 0; q < 4; q++) c[i][j][q] = 0.f;

    auto issue = [&](int ch) {
        int buf = ch & 1;
        int k0v = ch * BK;
        int region = k0v / K;
        int kreal  = k0v - region * K;
        const __half* As = (region == 1) ? Alo : Ahi;
        uint32_t baseA = sptr(&sA[buf][0]);
        uint32_t baseB = sptr(&sB[buf][0]);
        #pragma unroll
        for (int i = 0; i < 4; i++) {
            int row = rbase + 32 * i;
            int gm  = bm + row;
            bool ok = gm < M;
            const __half* src = As + (size_t)(ok ? gm : 0) * K + kreal + chunk * 8;
            cpa16(baseA + row * 128 + ((chunk ^ (row & 7)) << 4), src, ok);
        }
        #pragma unroll
        for (int i = 0; i < 2; i++) {
            int row = rbase + 32 * i;
            const __half* src = Whi + (size_t)(nb + row) * K + kreal + chunk * 8;
            cpa16(baseB + row * 128 + ((chunk ^ (row & 7)) << 4), src, true);
        }
        cpa_commit();
    };

    auto compute = [&](int buf) {
        uint32_t baseA = sptr(&sA[buf][0]);
        uint32_t baseB = sptr(&sB[buf][0]);
        #pragma unroll
        for (int kk = 0; kk < 4; kk++) {
            int cl = kk * 2 + (lane >> 4);
            uint32_t bf[2][4];
            #pragma unroll
            for (int h = 0; h < 2; h++) {
                int row = wn + h * 16 + (lane & 15);
                uint32_t p = baseB + row * 128 + ((cl ^ (row & 7)) << 4);
                asm volatile("ldmatrix.sync.aligned.m8n8.x4.shared.b16 {%0,%1,%2,%3}, [%4];"
                             : "=r"(bf[h][0]), "=r"(bf[h][1]), "=r"(bf[h][2]), "=r"(bf[h][3]) : "r"(p));
            }
            #pragma unroll
            for (int fi = 0; fi < 2; fi++) {
                uint32_t a0, a1, a2, a3;
                int row = wm + fi * 16 + (lane & 15);
                uint32_t p = baseA + row * 128 + ((cl ^ (row & 7)) << 4);
                asm volatile("ldmatrix.sync.aligned.m8n8.x4.shared.b16 {%0,%1,%2,%3}, [%4];"
                             : "=r"(a0), "=r"(a1), "=r"(a2), "=r"(a3) : "r"(p));
                #pragma unroll
                for (int h = 0; h < 2; h++) {
                    asm volatile("mma.sync.aligned.m16n8k16.row.col.f32.f16.f16.f32 "
                                 "{%0,%1,%2,%3}, {%4,%5,%6,%7}, {%8,%9}, {%0,%1,%2,%3};"
                                 : "+f"(c[fi][2*h+0][0]), "+f"(c[fi][2*h+0][1]), "+f"(c[fi][2*h+0][2]), "+f"(c[fi][2*h+0][3])
                                 : "r"(a0), "r"(a1), "r"(a2), "r"(a3), "r"(bf[h][0]), "r"(bf[h][2]));
                    asm volatile("mma.sync.aligned.m16n8k16.row.col.f32.f16.f16.f32 "
                                 "{%0,%1,%2,%3}, {%4,%5,%6,%7}, {%8,%9}, {%0,%1,%2,%3};"
                                 : "+f"(c[fi][2*h+1][0]), "+f"(c[fi][2*h+1][1]), "+f"(c[fi][2*h+1][2]), "+f"(c[fi][2*h+1][3])
                                 : "r"(a0), "r"(a1), "r"(a2), "r"(a3), "r"(bf[h][1]), "r"(bf[h][3]));
                }
            }
        }
    };

    issue(0);
    if (nch > 1) issue(1);
    for (int ch = 0; ch < nch; ch++) {
        if (ch + 1 < nch) asm volatile("cp.async.wait_group 1;" ::: "memory");
        else              asm volatile("cp.async.wait_group 0;" ::: "memory");
        __syncthreads();
        compute(ch & 1);
        __syncthreads();
        if (ch + 2 < nch) issue(ch + 2);
    }

    // ---- epilogue ----
    __half* dst;
    int stride, cb;
    if (OUTMODE == 1) {
        dst    = useB ? out1 : out0;
        stride = useB ? 512 : 256;
        cb     = nb;
    } else {
        dst    = out0;
        stride = ostride;
        cb     = bn;
    }
    #pragma unroll
    for (int fi = 0; fi < 2; fi++) {
        int row0 = bm + wm + fi * 16 + (lane >> 2);
        #pragma unroll
        for (int nj = 0; nj < 4; nj++) {
            int cl = wn + nj * 8 + (lane & 3) * 2;
            float bx = 0.f, by = 0.f;
            if (OUTMODE == 1) { bx = bias[bn + cl]; by = bias[bn + cl + 1]; }
            float v0 = c[fi][nj][0] + bx, v1 = c[fi][nj][1] + by;
            float v2 = c[fi][nj][2] + bx, v3 = c[fi][nj][3] + by;
            int col = cb + cl;
            if (row0 < M)
                *reinterpret_cast<__half2*>(&dst[(size_t)row0 * stride + col]) = __floats2half2_rn(v0, v1);
            if (row0 + 8 < M)
                *reinterpret_cast<__half2*>(&dst[(size_t)(row0 + 8) * stride + col]) = __floats2half2_rn(v2, v3);
        }
    }
}

// Batched Wc precompute: Wc[l] = Ws_uniform[l](split) @ WlT[l]  -> fp16 [512, K_l]
__global__ void __launch_bounds__(256) wc_gemm() {
    int l  = blockIdx.z;
    int bn = blockIdx.y * 64;
    int nout = (l == 0) ? 64 : 256;
    if (bn >= nout) return;
    gemm_core<2, false>(g_Wshi[l], g_Wslo[l], g_WlThi[l], nullptr,
                        nullptr, g_Wchi[l], nullptr, 512, 256, nout,
                        blockIdx.x * 128, bn);
}

// Fused per-layer GEMM: [Hhi | AB] = relu_in @ [Wlin ; Wc]^T + b768
__global__ void __launch_bounds__(256) layer_gemm(
    const __half* __restrict__ Ahi, const __half* __restrict__ Alo,
    int l, int K, __half* __restrict__ Hhi, __half* __restrict__ AB)
{
    gemm_core<1, true>(Ahi, Alo, g_Wlhi[l], g_Wchi[l],
                       g_b768[l], Hhi, AB, NNODES, K, 0,
                       blockIdx.x * 128, blockIdx.y * 64);
}

// ============================================================================
// CSR build (g_cnt zeroed by cvt_all)
// ============================================================================
__global__ void hist_kernel(const int* __restrict__ ei) {
    int e = blockIdx.x * blockDim.x + threadIdx.x;
    if (e < NEDGES) atomicAdd(&g_cnt[ei[NEDGES + e]], 1);
}

__global__ void scan_kernel() {  // 1 block, 1024 threads, warp-shuffle scan
    __shared__ int wsum[32];
    __shared__ int carry_s;
    const int t = threadIdx.x, lane = t & 31, w = t >> 5;
    if (t == 0) carry_s = 0;
    __syncthreads();
    for (int base = 0; base < NNODES; base += 1024) {
        int i = base + t;
        int v = (i < NNODES) ? g_cnt[i] : 0;
        int x = v;
        #pragma unroll
        for (int o = 1; o < 32; o <<= 1) {
            int y = __shfl_up_sync(0xffffffffu, x, o);
            if (lane >= o) x += y;
        }
        if (lane == 31) wsum[w] = x;
        __syncthreads();
        if (w == 0) {
            int s = wsum[lane];
            #pragma unroll
            for (int o = 1; o < 32; o <<= 1) {
                int y = __shfl_up_sync(0xffffffffu, s, o);
                if (lane >= o) s += y;
            }
            wsum[lane] = s;
        }
        __syncthreads();
        int incl  = x + (w > 0 ? wsum[w - 1] : 0);
        int carry = carry_s;
        if (i < NNODES) { g_rowptr[i] = carry + incl - v; g_cnt[i] = 0; }
        __syncthreads();
        if (t == 1023) carry_s = carry + incl;
        __syncthreads();
    }
    if (t == 0) g_rowptr[NNODES] = carry_s;
}

__global__ void scatter_kernel(const int* __restrict__ ei) {
    int e = blockIdx.x * blockDim.x + threadIdx.x;
    if (e < NEDGES) {
        int s = ei[e];
        int d = ei[NEDGES + e];
        int pos = g_rowptr[d] + atomicAdd(&g_cnt[d], 1);
        g_col[pos] = s;
    }
}

// ============================================================================
// Fused score + aggregate: one warp per dst node (CSR), no atomics.
// MODE 0: write relu-split hi/lo fp16. MODE 1: write fp32 (final output).
// ============================================================================
template<int MODE>
__global__ void __launch_bounds__(256) agg_kernel(
    const __half* __restrict__ AB,
    const __half* __restrict__ Hhi,
    const float* __restrict__ w2, const float* __restrict__ b2,
    float* __restrict__ outf, __half* __restrict__ ohi, __half* __restrict__ olo)
{
    const int lane = threadIdx.x & 31;
    const int d    = blockIdx.x * (blockDim.x >> 5) + (threadIdx.x >> 5);
    if (d >= NNODES) return;

    const float4 w0 = *reinterpret_cast<const float4*>(&w2[lane * 8]);
    const float4 w1 = *reinterpret_cast<const float4*>(&w2[lane * 8 + 4]);
    const float  bb = b2[0];

    uint4 araw = *reinterpret_cast<const uint4*>(&AB[(size_t)d * (2 * CH) + lane * 8]);
    float2 a0 = __half22float2(*reinterpret_cast<__half2*>(&araw.x));
    float2 a1 = __half22float2(*reinterpret_cast<__half2*>(&araw.y));
    float2 a2 = __half22float2(*reinterpret_cast<__half2*>(&araw.z));
    float2 a3 = __half22float2(*reinterpret_cast<__half2*>(&araw.w));

    float acc0 = 0.f, acc1 = 0.f, acc2 = 0.f, acc3 = 0.f;
    float acc4 = 0.f, acc5 = 0.f, acc6 = 0.f, acc7 = 0.f;

    const int beg = g_rowptr[d];
    const int end = g_rowptr[d + 1];

    for (int i = beg - 1; i < end; ++i) {
        int s = (i < beg) ? d : g_col[i];

        uint4 braw = *reinterpret_cast<const uint4*>(&AB[(size_t)s * (2 * CH) + CH + lane * 8]);
        uint4 hraw = *reinterpret_cast<const uint4*>(&Hhi[(size_t)s * CH + lane * 8]);

        float2 b0 = __half22float2(*reinterpret_cast<__half2*>(&braw.x));
        float2 b1 = __half22float2(*reinterpret_cast<__half2*>(&braw.y));
        float2 b2v = __half22float2(*reinterpret_cast<__half2*>(&braw.z));
        float2 b3 = __half22float2(*reinterpret_cast<__half2*>(&braw.w));

        float p;
        p  = fmaxf(a0.x + b0.x, 0.f) * w0.x;
        p += fmaxf(a0.y + b0.y, 0.f) * w0.y;
        p += fmaxf(a1.x + b1.x, 0.f) * w0.z;
        p += fmaxf(a1.y + b1.y, 0.f) * w0.w;
        p += fmaxf(a2.x + b2v.x, 0.f) * w1.x;
        p += fmaxf(a2.y + b2v.y, 0.f) * w1.y;
        p += fmaxf(a3.x + b3.x, 0.f) * w1.z;
        p += fmaxf(a3.y + b3.y, 0.f) * w1.w;

        #pragma unroll
        for (int off = 16; off > 0; off >>= 1)
            p += __shfl_xor_sync(0xffffffffu, p, off);

        float score = 1.f / (1.f + __expf(-(p + bb)));

        float2 h0 = __half22float2(*reinterpret_cast<__half2*>(&hraw.x));
        float2 h1 = __half22float2(*reinterpret_cast<__half2*>(&hraw.y));
        float2 h2 = __half22float2(*reinterpret_cast<__half2*>(&hraw.z));
        float2 h3 = __half22float2(*reinterpret_cast<__half2*>(&hraw.w));

        acc0 = fmaf(score, h0.x, acc0);
        acc1 = fmaf(score, h0.y, acc1);
        acc2 = fmaf(score, h1.x, acc2);
        acc3 = fmaf(score, h1.y, acc3);
        acc4 = fmaf(score, h2.x, acc4);
        acc5 = fmaf(score, h2.y, acc5);
        acc6 = fmaf(score, h3.x, acc6);
        acc7 = fmaf(score, h3.y, acc7);
    }

    if (MODE == 1) {
        float* op = &outf[(size_t)d * CH + lane * 8];
        *reinterpret_cast<float4*>(op)     = make_float4(acc0, acc1, acc2, acc3);
        *reinterpret_cast<float4*>(op + 4) = make_float4(acc4, acc5, acc6, acc7);
    } else {
        float r[8] = {fmaxf(acc0, 0.f), fmaxf(acc1, 0.f), fmaxf(acc2, 0.f), fmaxf(acc3, 0.f),
                      fmaxf(acc4, 0.f), fmaxf(acc5, 0.f), fmaxf(acc6, 0.f), fmaxf(acc7, 0.f)};
        __half h[8], l[8];
        #pragma unroll
        for (int q = 0; q < 8; q++) {
            h[q] = __float2half_rn(r[q]);
            l[q] = __float2half_rn(r[q] - __half2float(h[q]));
        }
        uint4 hv, lv;
        hv.x = *reinterpret_cast<unsigned*>(&__halves2half2(h[0], h[1]));
        hv.y = *reinterpret_cast<unsigned*>(&__halves2half2(h[2], h[3]));
        hv.z = *reinterpret_cast<unsigned*>(&__halves2half2(h[4], h[5]));
        hv.w = *reinterpret_cast<unsigned*>(&__halves2half2(h[6], h[7]));
        lv.x = *reinterpret_cast<unsigned*>(&__halves2half2(l[0], l[1]));
        lv.y = *reinterpret_cast<unsigned*>(&__halves2half2(l[2], l[3]));
        lv.z = *reinterpret_cast<unsigned*>(&__halves2half2(l[4], l[5]));
        lv.w = *reinterpret_cast<unsigned*>(&__halves2half2(l[6], l[7]));
        *reinterpret_cast<uint4*>(&ohi[(size_t)d * CH + lane * 8]) = hv;
        *reinterpret_cast<uint4*>(&olo[(size_t)d * CH + lane * 8]) = lv;
    }
}

extern "C" void kernel_launch(void* const* d_in, const int* in_sizes, int n_in,
                              void* d_out, int out_size)
{
    (void)in_sizes; (void)n_in; (void)out_size;
    const float* x  = (const float*)d_in[0];
    const int*   ei = (const int*)d_in[1];
    const float* W_lin[3] = {(const float*)d_in[2],  (const float*)d_in[8],  (const float*)d_in[14]};
    const float* b_lin[3] = {(const float*)d_in[3],  (const float*)d_in[9],  (const float*)d_in[15]};
    const float* W_s1[3]  = {(const float*)d_in[4],  (const float*)d_in[10], (const float*)d_in[16]};
    const float* b_s1[3]  = {(const float*)d_in[5],  (const float*)d_in[11], (const float*)d_in[17]};
    const float* W_s2[3]  = {(const float*)d_in[6],  (const float*)d_in[12], (const float*)d_in[18]};
    const float* b_s2[3]  = {(const float*)d_in[7],  (const float*)d_in[13], (const float*)d_in[19]};

    __half *xhi, *xlo, *Hhi, *Ahi, *Alo, *AB;
    cudaGetSymbolAddress((void**)&xhi, g_xhi);
    cudaGetSymbolAddress((void**)&xlo, g_xlo);
    cudaGetSymbolAddress((void**)&Hhi, g_Hhi);
    cudaGetSymbolAddress((void**)&Ahi, g_Ahi);
    cudaGetSymbolAddress((void**)&Alo, g_Alo);
    cudaGetSymbolAddress((void**)&AB,  g_AB);
    float* out = (float*)d_out;

    const dim3 blk(256);
    const dim3 gL((NNODES + 127) / 128, 768 / 64);   // (79, 12)
    const dim3 gWc(4, 4, 3);
    const int  agrid = (NNODES + 7) / 8;

    // ---- one-shot weight prep ----
    cvt_all<<<(S_END + 255) / 256, blk>>>(x, W_lin[0], W_lin[1], W_lin[2],
                                          W_s1[0], W_s1[1], W_s1[2]);
    bias_kernel<<<(3 * 768 + 255) / 256, blk>>>(b_lin[0], b_lin[1], b_lin[2],
                                                W_s1[0], W_s1[1], W_s1[2],
                                                b_s1[0], b_s1[1], b_s1[2]);
    wc_gemm<<<gWc, blk>>>();

    // ---- CSR build (dst-keyed) ----
    hist_kernel<<<(NEDGES + 255) / 256, blk>>>(ei);
    scan_kernel<<<1, 1024>>>();
    scatter_kernel<<<(NEDGES + 255) / 256, blk>>>(ei);

    // ---- layer 1 ----
    layer_gemm<<<gL, blk>>>(xhi, xlo, 0, 64, Hhi, AB);
    agg_kernel<0><<<agrid, blk>>>(AB, Hhi, W_s2[0], b_s2[0], nullptr, Ahi, Alo);

    // ---- layer 2 ----
    layer_gemm<<<gL, blk>>>(Ahi, Alo, 1, 256, Hhi, AB);
    agg_kernel<0><<<agrid, blk>>>(AB, Hhi, W_s2[1], b_s2[1], nullptr, Ahi, Alo);

    // ---- layer 3 (writes d_out) ----
    layer_gemm<<<gL, blk>>>(Ahi, Alo, 2, 256, Hhi, AB);
    agg_kernel<1><<<agrid, blk>>>(AB, Hhi, W_s2[2], b_s2[2], out, nullptr, nullptr);
}

// round 9
// speedup vs baseline: 1.3524x; 1.0264x over previous
#include <cuda_runtime.h>
#include <cuda_fp16.h>
#include <cstdint>

#define NNODES 10000
#define NEDGES 320000
#define CH     256

// ---- scratch (static device allocations; no cudaMalloc allowed) ----
__device__ __align__(16) __half g_xhi[NNODES * 64];
__device__ __align__(16) __half g_xlo[NNODES * 64];
__device__ __align__(16) __half g_Hhi[NNODES * CH];
__device__ __align__(16) __half g_Ahi[NNODES * CH];   // relu(agg) split, next-layer input
__device__ __align__(16) __half g_Alo[NNODES * CH];
__device__ __align__(16) __half g_AB [NNODES * 2 * CH];
__device__ __align__(16) __half g_Wlhi[3][CH * CH];       // W_lin fp16 (layer0: 256x64)
__device__ __align__(16) __half g_WlThi[3][CH * CH];      // W_lin^T fp16 (rows k_in, cols m)
__device__ __align__(16) __half g_Wshi[3][2 * CH * CH];   // W_s1 uniform [512,256] split
__device__ __align__(16) __half g_Wslo[3][2 * CH * CH];
__device__ __align__(16) __half g_Wchi[3][2 * CH * CH];   // Wc = Ws @ Wlin  [512, K_l] fp16
__device__ float g_b768[3][768];                          // [b_lin | Ws@b_lin + b_s1pad]
__device__ int g_rowptr[NNODES + 1];
__device__ int g_cnt[NNODES];
__device__ int g_col[NEDGES];

__device__ __forceinline__ uint32_t sptr(const void* p) {
    return (uint32_t)__cvta_generic_to_shared(p);
}
__device__ __forceinline__ void cpa16(uint32_t dst, const void* src, bool pred) {
    int sz = pred ? 16 : 0;
    asm volatile("cp.async.cg.shared.global [%0], [%1], 16, %2;"
                 :: "r"(dst), "l"(src), "r"(sz));
}
__device__ __forceinline__ void cpa_commit() {
    asm volatile("cp.async.commit_group;" ::: "memory");
}

// ============================================================================
// ONE fused prep kernel: x split, Wlin fp16, Wlin^T fp16, Ws uniform split,
// fused bias b768, g_cnt zeroing.
// ============================================================================
#define CX    (NNODES * 64)
#define S_WL0 (CX)
#define S_WL1 (S_WL0 + 16384)
#define S_WL2 (S_WL1 + 65536)
#define S_WT0 (S_WL2 + 65536)
#define S_WT1 (S_WT0 + 16384)
#define S_WT2 (S_WT1 + 65536)
#define S_WS0 (S_WT2 + 65536)
#define S_WS1 (S_WS0 + 131072)
#define S_WS2 (S_WS1 + 131072)
#define S_CNT (S_WS2 + 131072)
#define S_B   (S_CNT + NNODES)
#define S_END (S_B + 3 * 768)

__global__ void __launch_bounds__(256) cvt_all(
    const float* __restrict__ x,
    const float* __restrict__ Wl1, const float* __restrict__ Wl2, const float* __restrict__ Wl3,
    const float* __restrict__ Ws1, const float* __restrict__ Ws2, const float* __restrict__ Ws3,
    const float* __restrict__ bl1, const float* __restrict__ bl2, const float* __restrict__ bl3,
    const float* __restrict__ bs1, const float* __restrict__ bs2, const float* __restrict__ bs3)
{
    int i = blockIdx.x * blockDim.x + threadIdx.x;
    if (i >= S_END) return;
    if (i < CX) {
        float v = x[i];
        __half h = __float2half_rn(v);
        g_xhi[i] = h;
        g_xlo[i] = __float2half_rn(v - __half2float(h));
        return;
    }
    if (i < S_WT0) {   // Wlin fp16 copy
        int l, j; const float* W;
        if (i < S_WL1)      { l = 0; j = i - S_WL0; W = Wl1; }
        else if (i < S_WL2) { l = 1; j = i - S_WL1; W = Wl2; }
        else                { l = 2; j = i - S_WL2; W = Wl3; }
        g_Wlhi[l][j] = __float2half_rn(W[j]);
        return;
    }
    if (i < S_WS0) {   // Wlin^T fp16: [k_in][m] from Wlin[m*kin + k]
        int l, j, kin; const float* W;
        if (i < S_WT1)      { l = 0; j = i - S_WT0; W = Wl1; kin = 64; }
        else if (i < S_WT2) { l = 1; j = i - S_WT1; W = Wl2; kin = 256; }
        else                { l = 2; j = i - S_WT2; W = Wl3; kin = 256; }
        int k = j >> 8, m = j & 255;
        g_WlThi[l][j] = __float2half_rn(W[m * kin + k]);
        return;
    }
    if (i < S_CNT) {   // Ws uniform repack + hi/lo split
        int l, j; const float* W;
        if (i < S_WS1)      { l = 0; j = i - S_WS0; W = Ws1; }
        else if (i < S_WS2) { l = 1; j = i - S_WS1; W = Ws2; }
        else                { l = 2; j = i - S_WS2; W = Ws3; }
        int r = j >> 8, k = j & 255;
        float v = (r < CH) ? W[r * 2 * CH + k] : W[(r - CH) * 2 * CH + CH + k];
        __half h = __float2half_rn(v);
        g_Wshi[l][j] = h;
        g_Wslo[l][j] = __float2half_rn(v - __half2float(h));
        return;
    }
    if (i < S_B) { g_cnt[i - S_CNT] = 0; return; }
    {   // fused bias: b768[l] = [b_lin | Ws@b_lin + b_s1pad]
        int q = i - S_B;
        int l = q / 768, j = q % 768;
        const float* bl = (l == 0) ? bl1 : (l == 1) ? bl2 : bl3;
        const float* Ws = (l == 0) ? Ws1 : (l == 1) ? Ws2 : Ws3;
        const float* bs = (l == 0) ? bs1 : (l == 1) ? bs2 : bs3;
        if (j < 256) { g_b768[l][j] = bl[j]; return; }
        int r = j - 256;
        float acc = (r < CH) ? bs[r] : 0.f;
        for (int m = 0; m < 256; m++) {
            float w = (r < CH) ? Ws[r * 2 * CH + m] : Ws[(r - CH) * 2 * CH + CH + m];
            acc += w * bl[m];
        }
        g_b768[l][j] = acc;
    }
}

// ============================================================================
// GEMM core: 2-region split (A = hi+lo exact vs fp16 W; W fp16 single).
// Virtual K' = 2K over regions: (Ahi,W), (Alo,W).
// BM=128 BN=64 BK=64, 8 warps, warp tile 32x32 (4M x 2N), 2-stage cp.async,
// 128B-row XOR swizzle.
// DUALW: weight rows n<256 from Wa, n>=256 from Wb (both stride K).
// OUTMODE 1: dual single-fp16 out (n<256 -> out0 stride 256, else out1 stride 512), +bias.
// OUTMODE 2: single fp16 out0 stride ostride, no bias.
// ============================================================================
template<int OUTMODE, bool DUALW>
__device__ __forceinline__ void gemm_core(
    const __half* __restrict__ Ahi, const __half* __restrict__ Alo,
    const __half* __restrict__ Wahi, const __half* __restrict__ Wbhi,
    const float* __restrict__ bias,
    __half* __restrict__ out0, __half* __restrict__ out1,
    int M, int K, int ostride, int bm, int bn)
{
    constexpr int BM = 128, BN = 64, BK = 64;
    __shared__ __align__(16) __half sA[2][BM * BK];   // 32 KB
    __shared__ __align__(16) __half sB[2][BN * BK];   // 16 KB

    const int tid  = threadIdx.x;
    const int lane = tid & 31;
    const int warp = tid >> 5;
    const int wm   = (warp >> 1) * 32;
    const int wn   = (warp & 1) * 32;
    const int nch  = (2 * K) / BK;

    const int chunk = tid & 7;
    const int rbase = tid >> 3;

    const bool useB = DUALW && (bn >= 256);
    const int  nb   = useB ? bn - 256 : bn;
    const __half* Whi = useB ? Wbhi : Wahi;

    float c[2][4][4];
    #pragma unroll
    for (int i = 0; i < 2; i++)
        #pragma unroll
        for (int j = 0; j < 4; j++)
            #pragma unroll
            for (int q = 0; q < 4; q++) c[i][j][q] = 0.f;

    auto issue = [&](int ch) {
        int buf = ch & 1;
        int k0v = ch * BK;
        int region = k0v / K;
        int kreal  = k0v - region * K;
        const __half* As = (region == 1) ? Alo : Ahi;
        uint32_t baseA = sptr(&sA[buf][0]);
        uint32_t baseB = sptr(&sB[buf][0]);
        #pragma unroll
        for (int i = 0; i < 4; i++) {
            int row = rbase + 32 * i;
            int gm  = bm + row;
            bool ok = gm < M;
            const __half* src = As + (size_t)(ok ? gm : 0) * K + kreal + chunk * 8;
            cpa16(baseA + row * 128 + ((chunk ^ (row & 7)) << 4), src, ok);
        }
        #pragma unroll
        for (int i = 0; i < 2; i++) {
            int row = rbase + 32 * i;
            const __half* src = Whi + (size_t)(nb + row) * K + kreal + chunk * 8;
            cpa16(baseB + row * 128 + ((chunk ^ (row & 7)) << 4), src, true);
        }
        cpa_commit();
    };

    auto compute = [&](int buf) {
        uint32_t baseA = sptr(&sA[buf][0]);
        uint32_t baseB = sptr(&sB[buf][0]);
        #pragma unroll
        for (int kk = 0; kk < 4; kk++) {
            int cl = kk * 2 + (lane >> 4);
            uint32_t bf[2][4];
            #pragma unroll
            for (int h = 0; h < 2; h++) {
                int row = wn + h * 16 + (lane & 15);
                uint32_t p = baseB + row * 128 + ((cl ^ (row & 7)) << 4);
                asm volatile("ldmatrix.sync.aligned.m8n8.x4.shared.b16 {%0,%1,%2,%3}, [%4];"
                             : "=r"(bf[h][0]), "=r"(bf[h][1]), "=r"(bf[h][2]), "=r"(bf[h][3]) : "r"(p));
            }
            #pragma unroll
            for (int fi = 0; fi < 2; fi++) {
                uint32_t a0, a1, a2, a3;
                int row = wm + fi * 16 + (lane & 15);
                uint32_t p = baseA + row * 128 + ((cl ^ (row & 7)) << 4);
                asm volatile("ldmatrix.sync.aligned.m8n8.x4.shared.b16 {%0,%1,%2,%3}, [%4];"
                             : "=r"(a0), "=r"(a1), "=r"(a2), "=r"(a3) : "r"(p));
                #pragma unroll
                for (int h = 0; h < 2; h++) {
                    asm volatile("mma.sync.aligned.m16n8k16.row.col.f32.f16.f16.f32 "
                                 "{%0,%1,%2,%3}, {%4,%5,%6,%7}, {%8,%9}, {%0,%1,%2,%3};"
                                 : "+f"(c[fi][2*h+0][0]), "+f"(c[fi][2*h+0][1]), "+f"(c[fi][2*h+0][2]), "+f"(c[fi][2*h+0][3])
                                 : "r"(a0), "r"(a1), "r"(a2), "r"(a3), "r"(bf[h][0]), "r"(bf[h][2]));
                    asm volatile("mma.sync.aligned.m16n8k16.row.col.f32.f16.f16.f32 "
                                 "{%0,%1,%2,%3}, {%4,%5,%6,%7}, {%8,%9}, {%0,%1,%2,%3};"
                                 : "+f"(c[fi][2*h+1][0]), "+f"(c[fi][2*h+1][1]), "+f"(c[fi][2*h+1][2]), "+f"(c[fi][2*h+1][3])
                                 : "r"(a0), "r"(a1), "r"(a2), "r"(a3), "r"(bf[h][1]), "r"(bf[h][3]));
                }
            }
        }
    };

    issue(0);
    if (nch > 1) issue(1);
    for (int ch = 0; ch < nch; ch++) {
        if (ch + 1 < nch) asm volatile("cp.async.wait_group 1;" ::: "memory");
        else              asm volatile("cp.async.wait_group 0;" ::: "memory");
        __syncthreads();
        compute(ch & 1);
        __syncthreads();
        if (ch + 2 < nch) issue(ch + 2);
    }

    // ---- epilogue ----
    __half* dst;
    int stride, cb;
    if (OUTMODE == 1) {
        dst    = useB ? out1 : out0;
        stride = useB ? 512 : 256;
        cb     = nb;
    } else {
        dst    = out0;
        stride = ostride;
        cb     = bn;
    }
    #pragma unroll
    for (int fi = 0; fi < 2; fi++) {
        int row0 = bm + wm + fi * 16 + (lane >> 2);
        #pragma unroll
        for (int nj = 0; nj < 4; nj++) {
            int cl = wn + nj * 8 + (lane & 3) * 2;
            float bx = 0.f, by = 0.f;
            if (OUTMODE == 1) { bx = bias[bn + cl]; by = bias[bn + cl + 1]; }
            float v0 = c[fi][nj][0] + bx, v1 = c[fi][nj][1] + by;
            float v2 = c[fi][nj][2] + bx, v3 = c[fi][nj][3] + by;
            int col = cb + cl;
            if (row0 < M)
                *reinterpret_cast<__half2*>(&dst[(size_t)row0 * stride + col]) = __floats2half2_rn(v0, v1);
            if (row0 + 8 < M)
                *reinterpret_cast<__half2*>(&dst[(size_t)(row0 + 8) * stride + col]) = __floats2half2_rn(v2, v3);
        }
    }
}

// Batched Wc precompute: Wc[l] = Ws_uniform[l](split) @ WlT[l]  -> fp16 [512, K_l]
__global__ void __launch_bounds__(256) wc_gemm() {
    int l  = blockIdx.z;
    int bn = blockIdx.y * 64;
    int nout = (l == 0) ? 64 : 256;
    if (bn >= nout) return;
    gemm_core<2, false>(g_Wshi[l], g_Wslo[l], g_WlThi[l], nullptr,
                        nullptr, g_Wchi[l], nullptr, 512, 256, nout,
                        blockIdx.x * 128, bn);
}

// Fused per-layer GEMM: [Hhi | AB] = relu_in @ [Wlin ; Wc]^T + b768
__global__ void __launch_bounds__(256) layer_gemm(
    const __half* __restrict__ Ahi, const __half* __restrict__ Alo,
    int l, int K, __half* __restrict__ Hhi, __half* __restrict__ AB)
{
    gemm_core<1, true>(Ahi, Alo, g_Wlhi[l], g_Wchi[l],
                       g_b768[l], Hhi, AB, NNODES, K, 0,
                       blockIdx.x * 128, blockIdx.y * 64);
}

// ============================================================================
// CSR build (g_cnt zeroed by cvt_all)
// ============================================================================
__global__ void hist_kernel(const int* __restrict__ ei) {
    int e = blockIdx.x * blockDim.x + threadIdx.x;
    if (e < NEDGES) atomicAdd(&g_cnt[ei[NEDGES + e]], 1);
}

__global__ void scan_kernel() {  // 1 block, 1024 threads, warp-shuffle scan
    __shared__ int wsum[32];
    __shared__ int carry_s;
    const int t = threadIdx.x, lane = t & 31, w = t >> 5;
    if (t == 0) carry_s = 0;
    __syncthreads();
    for (int base = 0; base < NNODES; base += 1024) {
        int i = base + t;
        int v = (i < NNODES) ? g_cnt[i] : 0;
        int x = v;
        #pragma unroll
        for (int o = 1; o < 32; o <<= 1) {
            int y = __shfl_up_sync(0xffffffffu, x, o);
            if (lane >= o) x += y;
        }
        if (lane == 31) wsum[w] = x;
        __syncthreads();
        if (w == 0) {
            int s = wsum[lane];
            #pragma unroll
            for (int o = 1; o < 32; o <<= 1) {
                int y = __shfl_up_sync(0xffffffffu, s, o);
                if (lane >= o) s += y;
            }
            wsum[lane] = s;
        }
        __syncthreads();
        int incl  = x + (w > 0 ? wsum[w - 1] : 0);
        int carry = carry_s;
        if (i < NNODES) { g_rowptr[i] = carry + incl - v; g_cnt[i] = 0; }
        __syncthreads();
        if (t == 1023) carry_s = carry + incl;
        __syncthreads();
    }
    if (t == 0) g_rowptr[NNODES] = carry_s;
}

__global__ void scatter_kernel(const int* __restrict__ ei) {
    int e = blockIdx.x * blockDim.x + threadIdx.x;
    if (e < NEDGES) {
        int s = ei[e];
        int d = ei[NEDGES + e];
        int pos = g_rowptr[d] + atomicAdd(&g_cnt[d], 1);
        g_col[pos] = s;
    }
}

// ============================================================================
// Fused score + aggregate: one warp per dst node (CSR), no atomics.
// 2-edge ILP: independent per-edge chains interleaved to hide SHFL/sigmoid
// latency. MODE 0: relu-split hi/lo fp16 out. MODE 1: fp32 out (final).
// ============================================================================
template<int MODE>
__global__ void __launch_bounds__(256) agg_kernel(
    const __half* __restrict__ AB,
    const __half* __restrict__ Hhi,
    const float* __restrict__ w2, const float* __restrict__ b2,
    float* __restrict__ outf, __half* __restrict__ ohi, __half* __restrict__ olo)
{
    const int lane = threadIdx.x & 31;
    const int d    = blockIdx.x * (blockDim.x >> 5) + (threadIdx.x >> 5);
    if (d >= NNODES) return;

    const float4 w0 = *reinterpret_cast<const float4*>(&w2[lane * 8]);
    const float4 w1 = *reinterpret_cast<const float4*>(&w2[lane * 8 + 4]);
    const float  bb = b2[0];

    uint4 araw = *reinterpret_cast<const uint4*>(&AB[(size_t)d * (2 * CH) + lane * 8]);
    float2 a0 = __half22float2(*reinterpret_cast<__half2*>(&araw.x));
    float2 a1 = __half22float2(*reinterpret_cast<__half2*>(&araw.y));
    float2 a2 = __half22float2(*reinterpret_cast<__half2*>(&araw.z));
    float2 a3 = __half22float2(*reinterpret_cast<__half2*>(&araw.w));

    float acc0 = 0.f, acc1 = 0.f, acc2 = 0.f, acc3 = 0.f;
    float acc4 = 0.f, acc5 = 0.f, acc6 = 0.f, acc7 = 0.f;

    // partial score (pre-reduce) for one source node
    auto partial = [&](int s, uint4& hraw) -> float {
        uint4 braw = *reinterpret_cast<const uint4*>(&AB[(size_t)s * (2 * CH) + CH + lane * 8]);
        hraw = *reinterpret_cast<const uint4*>(&Hhi[(size_t)s * CH + lane * 8]);
        float2 b0 = __half22float2(*reinterpret_cast<__half2*>(&braw.x));
        float2 b1 = __half22float2(*reinterpret_cast<__half2*>(&braw.y));
        float2 b2v = __half22float2(*reinterpret_cast<__half2*>(&braw.z));
        float2 b3 = __half22float2(*reinterpret_cast<__half2*>(&braw.w));
        float p;
        p  = fmaxf(a0.x + b0.x, 0.f) * w0.x;
        p += fmaxf(a0.y + b0.y, 0.f) * w0.y;
        p += fmaxf(a1.x + b1.x, 0.f) * w0.z;
        p += fmaxf(a1.y + b1.y, 0.f) * w0.w;
        p += fmaxf(a2.x + b2v.x, 0.f) * w1.x;
        p += fmaxf(a2.y + b2v.y, 0.f) * w1.y;
        p += fmaxf(a3.x + b3.x, 0.f) * w1.z;
        p += fmaxf(a3.y + b3.y, 0.f) * w1.w;
        return p;
    };

    auto accum = [&](float score, const uint4& hraw) {
        float2 h0 = __half22float2(*reinterpret_cast<const __half2*>(&hraw.x));
        float2 h1 = __half22float2(*reinterpret_cast<const __half2*>(&hraw.y));
        float2 h2 = __half22float2(*reinterpret_cast<const __half2*>(&hraw.z));
        float2 h3 = __half22float2(*reinterpret_cast<const __half2*>(&hraw.w));
        acc0 = fmaf(score, h0.x, acc0);
        acc1 = fmaf(score, h0.y, acc1);
        acc2 = fmaf(score, h1.x, acc2);
        acc3 = fmaf(score, h1.y, acc3);
        acc4 = fmaf(score, h2.x, acc4);
        acc5 = fmaf(score, h2.y, acc5);
        acc6 = fmaf(score, h3.x, acc6);
        acc7 = fmaf(score, h3.y, acc7);
    };

    const int beg = g_rowptr[d];
    const int end = g_rowptr[d + 1];

    // self-loop first
    {
        uint4 hraw;
        float p = partial(d, hraw);
        #pragma unroll
        for (int off = 16; off > 0; off >>= 1)
            p += __shfl_xor_sync(0xffffffffu, p, off);
        accum(1.f / (1.f + __expf(-(p + bb))), hraw);
    }

    int i = beg;
    for (; i + 1 < end; i += 2) {
        int s0 = g_col[i];
        int s1 = g_col[i + 1];
        uint4 hraw0, hraw1;
        float p0 = partial(s0, hraw0);
        float p1 = partial(s1, hraw1);
        #pragma unroll
        for (int off = 16; off > 0; off >>= 1) {
            p0 += __shfl_xor_sync(0xffffffffu, p0, off);
            p1 += __shfl_xor_sync(0xffffffffu, p1, off);
        }
        float sc0 = 1.f / (1.f + __expf(-(p0 + bb)));
        float sc1 = 1.f / (1.f + __expf(-(p1 + bb)));
        accum(sc0, hraw0);
        accum(sc1, hraw1);
    }
    if (i < end) {
        uint4 hraw;
        float p = partial(g_col[i], hraw);
        #pragma unroll
        for (int off = 16; off > 0; off >>= 1)
            p += __shfl_xor_sync(0xffffffffu, p, off);
        accum(1.f / (1.f + __expf(-(p + bb))), hraw);
    }

    if (MODE == 1) {
        float* op = &outf[(size_t)d * CH + lane * 8];
        *reinterpret_cast<float4*>(op)     = make_float4(acc0, acc1, acc2, acc3);
        *reinterpret_cast<float4*>(op + 4) = make_float4(acc4, acc5, acc6, acc7);
    } else {
        float r[8] = {fmaxf(acc0, 0.f), fmaxf(acc1, 0.f), fmaxf(acc2, 0.f), fmaxf(acc3, 0.f),
                      fmaxf(acc4, 0.f), fmaxf(acc5, 0.f), fmaxf(acc6, 0.f), fmaxf(acc7, 0.f)};
        __half h[8], l[8];
        #pragma unroll
        for (int q = 0; q < 8; q++) {
            h[q] = __float2half_rn(r[q]);
            l[q] = __float2half_rn(r[q] - __half2float(h[q]));
        }
        uint4 hv, lv;
        hv.x = *reinterpret_cast<unsigned*>(&__halves2half2(h[0], h[1]));
        hv.y = *reinterpret_cast<unsigned*>(&__halves2half2(h[2], h[3]));
        hv.z = *reinterpret_cast<unsigned*>(&__halves2half2(h[4], h[5]));
        hv.w = *reinterpret_cast<unsigned*>(&__halves2half2(h[6], h[7]));
        lv.x = *reinterpret_cast<unsigned*>(&__halves2half2(l[0], l[1]));
        lv.y = *reinterpret_cast<unsigned*>(&__halves2half2(l[2], l[3]));
        lv.z = *reinterpret_cast<unsigned*>(&__halves2half2(l[4], l[5]));
        lv.w = *reinterpret_cast<unsigned*>(&__halves2half2(l[6], l[7]));
        *reinterpret_cast<uint4*>(&ohi[(size_t)d * CH + lane * 8]) = hv;
        *reinterpret_cast<uint4*>(&olo[(size_t)d * CH + lane * 8]) = lv;
    }
}

extern "C" void kernel_launch(void* const* d_in, const int* in_sizes, int n_in,
                              void* d_out, int out_size)
{
    (void)in_sizes; (void)n_in; (void)out_size;
    const float* x  = (const float*)d_in[0];
    const int*   ei = (const int*)d_in[1];
    const float* W_lin[3] = {(const float*)d_in[2],  (const float*)d_in[8],  (const float*)d_in[14]};
    const float* b_lin[3] = {(const float*)d_in[3],  (const float*)d_in[9],  (const float*)d_in[15]};
    const float* W_s1[3]  = {(const float*)d_in[4],  (const float*)d_in[10], (const float*)d_in[16]};
    const float* b_s1[3]  = {(const float*)d_in[5],  (const float*)d_in[11], (const float*)d_in[17]};
    const float* W_s2[3]  = {(const float*)d_in[6],  (const float*)d_in[12], (const float*)d_in[18]};
    const float* b_s2[3]  = {(const float*)d_in[7],  (const float*)d_in[13], (const float*)d_in[19]};

    __half *xhi, *xlo, *Hhi, *Ahi, *Alo, *AB;
    cudaGetSymbolAddress((void**)&xhi, g_xhi);
    cudaGetSymbolAddress((void**)&xlo, g_xlo);
    cudaGetSymbolAddress((void**)&Hhi, g_Hhi);
    cudaGetSymbolAddress((void**)&Ahi, g_Ahi);
    cudaGetSymbolAddress((void**)&Alo, g_Alo);
    cudaGetSymbolAddress((void**)&AB,  g_AB);
    float* out = (float*)d_out;

    const dim3 blk(256);
    const dim3 gL((NNODES + 127) / 128, 768 / 64);   // (79, 12)
    const dim3 gWc(4, 4, 3);
    const int  agrid = (NNODES + 7) / 8;

    // ---- one-shot prep (conversions + bias + cnt zero) ----
    cvt_all<<<(S_END + 255) / 256, blk>>>(x, W_lin[0], W_lin[1], W_lin[2],
                                          W_s1[0], W_s1[1], W_s1[2],
                                          b_lin[0], b_lin[1], b_lin[2],
                                          b_s1[0], b_s1[1], b_s1[2]);
    wc_gemm<<<gWc, blk>>>();

    // ---- CSR build (dst-keyed) ----
    hist_kernel<<<(NEDGES + 255) / 256, blk>>>(ei);
    scan_kernel<<<1, 1024>>>();
    scatter_kernel<<<(NEDGES + 255) / 256, blk>>>(ei);

    // ---- layer 1 ----
    layer_gemm<<<gL, blk>>>(xhi, xlo, 0, 64, Hhi, AB);
    agg_kernel<0><<<agrid, blk>>>(AB, Hhi, W_s2[0], b_s2[0], nullptr, Ahi, Alo);

    // ---- layer 2 ----
    layer_gemm<<<gL, blk>>>(Ahi, Alo, 1, 256, Hhi, AB);
    agg_kernel<0><<<agrid, blk>>>(AB, Hhi, W_s2[1], b_s2[1], nullptr, Ahi, Alo);

    // ---- layer 3 (writes d_out) ----
    layer_gemm<<<gL, blk>>>(Ahi, Alo, 2, 256, Hhi, AB);
    agg_kernel<1><<<agrid, blk>>>(AB, Hhi, W_s2[2], b_s2[2], out, nullptr, nullptr);
}

// round 10
// speedup vs baseline: 1.3788x; 1.0195x over previous
#include <cuda_runtime.h>
#include <cuda_fp16.h>
#include <cstdint>

#define NNODES 10000
#define NEDGES 320000
#define CH     256

// ---- scratch (static device allocations; no cudaMalloc allowed) ----
__device__ __align__(16) __half g_xhi[NNODES * 64];
__device__ __align__(16) __half g_xlo[NNODES * 64];
__device__ __align__(16) __half g_Hhi[NNODES * CH];
__device__ __align__(16) __half g_Ahi[NNODES * CH];   // relu(agg) split, next-layer input
__device__ __align__(16) __half g_Alo[NNODES * CH];
__device__ __align__(16) __half g_AB [NNODES * 2 * CH];
__device__ __align__(16) __half g_Wlhi[3][CH * CH];       // W_lin fp16 (layer0: 256x64)
__device__ __align__(16) __half g_WlThi[3][CH * CH];      // W_lin^T fp16 (rows k_in, cols m)
__device__ __align__(16) __half g_Wshi[3][2 * CH * CH];   // W_s1 uniform [512,256] split
__device__ __align__(16) __half g_Wslo[3][2 * CH * CH];
__device__ __align__(16) __half g_Wchi[3][2 * CH * CH];   // Wc = Ws @ Wlin  [512, K_l] fp16
__device__ float g_b768[3][768];                          // [b_lin | Ws@b_lin + b_s1pad]
__device__ int g_rowptr[NNODES + 1];
__device__ int g_cnt[NNODES];   // starts 0; hist fills; scatter's atomicSub restores to 0
__device__ int g_col[NEDGES];

__device__ __forceinline__ uint32_t sptr(const void* p) {
    return (uint32_t)__cvta_generic_to_shared(p);
}
__device__ __forceinline__ void cpa16(uint32_t dst, const void* src, bool pred) {
    int sz = pred ? 16 : 0;
    asm volatile("cp.async.cg.shared.global [%0], [%1], 16, %2;"
                 :: "r"(dst), "l"(src), "r"(sz));
}
__device__ __forceinline__ void cpa_commit() {
    asm volatile("cp.async.commit_group;" ::: "memory");
}

// ============================================================================
// ONE fused prep kernel: x split, Wlin fp16, Wlin^T fp16, Ws uniform split,
// fused bias b768, AND the dst histogram (g_cnt starts at 0 — restored by
// scatter's atomicSub on the previous launch/replay).
// ============================================================================
#define CX    (NNODES * 64)
#define S_WL0 (CX)
#define S_WL1 (S_WL0 + 16384)
#define S_WL2 (S_WL1 + 65536)
#define S_WT0 (S_WL2 + 65536)
#define S_WT1 (S_WT0 + 16384)
#define S_WT2 (S_WT1 + 65536)
#define S_WS0 (S_WT2 + 65536)
#define S_WS1 (S_WS0 + 131072)
#define S_WS2 (S_WS1 + 131072)
#define S_BIA (S_WS2 + 131072)
#define S_HST (S_BIA + 3 * 768)
#define S_END (S_HST + NEDGES)

__global__ void __launch_bounds__(256) cvt_all(
    const float* __restrict__ x, const int* __restrict__ ei,
    const float* __restrict__ Wl1, const float* __restrict__ Wl2, const float* __restrict__ Wl3,
    const float* __restrict__ Ws1, const float* __restrict__ Ws2, const float* __restrict__ Ws3,
    const float* __restrict__ bl1, const float* __restrict__ bl2, const float* __restrict__ bl3,
    const float* __restrict__ bs1, const float* __restrict__ bs2, const float* __restrict__ bs3)
{
    int i = blockIdx.x * blockDim.x + threadIdx.x;
    if (i >= S_END) return;
    if (i < CX) {
        float v = x[i];
        __half h = __float2half_rn(v);
        g_xhi[i] = h;
        g_xlo[i] = __float2half_rn(v - __half2float(h));
        return;
    }
    if (i < S_WT0) {   // Wlin fp16 copy
        int l, j; const float* W;
        if (i < S_WL1)      { l = 0; j = i - S_WL0; W = Wl1; }
        else if (i < S_WL2) { l = 1; j = i - S_WL1; W = Wl2; }
        else                { l = 2; j = i - S_WL2; W = Wl3; }
        g_Wlhi[l][j] = __float2half_rn(W[j]);
        return;
    }
    if (i < S_WS0) {   // Wlin^T fp16: [k_in][m] from Wlin[m*kin + k]
        int l, j, kin; const float* W;
        if (i < S_WT1)      { l = 0; j = i - S_WT0; W = Wl1; kin = 64; }
        else if (i < S_WT2) { l = 1; j = i - S_WT1; W = Wl2; kin = 256; }
        else                { l = 2; j = i - S_WT2; W = Wl3; kin = 256; }
        int k = j >> 8, m = j & 255;
        g_WlThi[l][j] = __float2half_rn(W[m * kin + k]);
        return;
    }
    if (i < S_BIA) {   // Ws uniform repack + hi/lo split
        int l, j; const float* W;
        if (i < S_WS1)      { l = 0; j = i - S_WS0; W = Ws1; }
        else if (i < S_WS2) { l = 1; j = i - S_WS1; W = Ws2; }
        else                { l = 2; j = i - S_WS2; W = Ws3; }
        int r = j >> 8, k = j & 255;
        float v = (r < CH) ? W[r * 2 * CH + k] : W[(r - CH) * 2 * CH + CH + k];
        __half h = __float2half_rn(v);
        g_Wshi[l][j] = h;
        g_Wslo[l][j] = __float2half_rn(v - __half2float(h));
        return;
    }
    if (i < S_HST) {   // fused bias: b768[l] = [b_lin | Ws@b_lin + b_s1pad]
        int q = i - S_BIA;
        int l = q / 768, j = q % 768;
        const float* bl = (l == 0) ? bl1 : (l == 1) ? bl2 : bl3;
        const float* Ws = (l == 0) ? Ws1 : (l == 1) ? Ws2 : Ws3;
        const float* bs = (l == 0) ? bs1 : (l == 1) ? bs2 : bs3;
        if (j < 256) { g_b768[l][j] = bl[j]; return; }
        int r = j - 256;
        float acc = (r < CH) ? bs[r] : 0.f;
        for (int m = 0; m < 256; m++) {
            float w = (r < CH) ? Ws[r * 2 * CH + m] : Ws[(r - CH) * 2 * CH + CH + m];
            acc += w * bl[m];
        }
        g_b768[l][j] = acc;
        return;
    }
    // dst histogram
    atomicAdd(&g_cnt[ei[NEDGES + (i - S_HST)]], 1);
}

// ============================================================================
// Single-pass scan: 1024 threads x 10 elements, 2 barriers total.
// Does NOT modify g_cnt (scatter restores it to zero).
// ============================================================================
__global__ void __launch_bounds__(1024) scan_kernel() {
    __shared__ int wsum[32];
    const int t = threadIdx.x, lane = t & 31, w = t >> 5;
    const int base_i = t * 10;
    int v[10];
    int s = 0;
    #pragma unroll
    for (int q = 0; q < 10; q++) {
        int idx = base_i + q;
        v[q] = (idx < NNODES) ? g_cnt[idx] : 0;
        s += v[q];
    }
    int x = s;
    #pragma unroll
    for (int o = 1; o < 32; o <<= 1) {
        int y = __shfl_up_sync(0xffffffffu, x, o);
        if (lane >= o) x += y;
    }
    if (lane == 31) wsum[w] = x;
    __syncthreads();
    if (w == 0) {
        int z = wsum[lane];
        #pragma unroll
        for (int o = 1; o < 32; o <<= 1) {
            int y = __shfl_up_sync(0xffffffffu, z, o);
            if (lane >= o) z += y;
        }
        wsum[lane] = z;
    }
    __syncthreads();
    int run = (x - s) + (w > 0 ? wsum[w - 1] : 0);   // exclusive prefix for this thread
    #pragma unroll
    for (int q = 0; q < 10; q++) {
        int idx = base_i + q;
        if (idx < NNODES) g_rowptr[idx] = run;
        run += v[q];
    }
    if (t == 1023) g_rowptr[NNODES] = wsum[31];
}

// scatter restores g_cnt to all-zero (atomicSub), keeping replays deterministic.
__global__ void scatter_kernel(const int* __restrict__ ei) {
    int e = blockIdx.x * blockDim.x + threadIdx.x;
    if (e < NEDGES) {
        int s = ei[e];
        int d = ei[NEDGES + e];
        int old = atomicSub(&g_cnt[d], 1);
        g_col[g_rowptr[d] + old - 1] = s;
    }
}

// ============================================================================
// GEMM core: 2-region split (A = hi+lo exact vs fp16 W; W fp16 single).
// Virtual K' = 2K over regions: (Ahi,W), (Alo,W).
// BM=128 BN=64 BK=64, 8 warps, warp tile 32x32 (4M x 2N), 2-stage cp.async,
// 128B-row XOR swizzle.
// DUALW: weight rows n<256 from Wa, n>=256 from Wb (both stride K).
// OUTMODE 1: dual single-fp16 out (n<256 -> out0 stride 256, else out1 stride 512), +bias.
// OUTMODE 2: single fp16 out0 stride ostride, no bias.
// ============================================================================
template<int OUTMODE, bool DUALW>
__device__ __forceinline__ void gemm_core(
    const __half* __restrict__ Ahi, const __half* __restrict__ Alo,
    const __half* __restrict__ Wahi, const __half* __restrict__ Wbhi,
    const float* __restrict__ bias,
    __half* __restrict__ out0, __half* __restrict__ out1,
    int M, int K, int ostride, int bm, int bn)
{
    constexpr int BM = 128, BN = 64, BK = 64;
    __shared__ __align__(16) __half sA[2][BM * BK];   // 32 KB
    __shared__ __align__(16) __half sB[2][BN * BK];   // 16 KB

    const int tid  = threadIdx.x;
    const int lane = tid & 31;
    const int warp = tid >> 5;
    const int wm   = (warp >> 1) * 32;
    const int wn   = (warp & 1) * 32;
    const int nch  = (2 * K) / BK;

    const int chunk = tid & 7;
    const int rbase = tid >> 3;

    const bool useB = DUALW && (bn >= 256);
    const int  nb   = useB ? bn - 256 : bn;
    const __half* Whi = useB ? Wbhi : Wahi;

    float c[2][4][4];
    #pragma unroll
    for (int i = 0; i < 2; i++)
        #pragma unroll
        for (int j = 0; j < 4; j++)
            #pragma unroll
            for (int q = 0; q < 4; q++) c[i][j][q] = 0.f;

    auto issue = [&](int ch) {
        int buf = ch & 1;
        int k0v = ch * BK;
        int region = k0v / K;
        int kreal  = k0v - region * K;
        const __half* As = (region == 1) ? Alo : Ahi;
        uint32_t baseA = sptr(&sA[buf][0]);
        uint32_t baseB = sptr(&sB[buf][0]);
        #pragma unroll
        for (int i = 0; i < 4; i++) {
            int row = rbase + 32 * i;
            int gm  = bm + row;
            bool ok = gm < M;
            const __half* src = As + (size_t)(ok ? gm : 0) * K + kreal + chunk * 8;
            cpa16(baseA + row * 128 + ((chunk ^ (row & 7)) << 4), src, ok);
        }
        #pragma unroll
        for (int i = 0; i < 2; i++) {
            int row = rbase + 32 * i;
            const __half* src = Whi + (size_t)(nb + row) * K + kreal + chunk * 8;
            cpa16(baseB + row * 128 + ((chunk ^ (row & 7)) << 4), src, true);
        }
        cpa_commit();
    };

    auto compute = [&](int buf) {
        uint32_t baseA = sptr(&sA[buf][0]);
        uint32_t baseB = sptr(&sB[buf][0]);
        #pragma unroll
        for (int kk = 0; kk < 4; kk++) {
            int cl = kk * 2 + (lane >> 4);
            uint32_t bf[2][4];
            #pragma unroll
            for (int h = 0; h < 2; h++) {
                int row = wn + h * 16 + (lane & 15);
                uint32_t p = baseB + row * 128 + ((cl ^ (row & 7)) << 4);
                asm volatile("ldmatrix.sync.aligned.m8n8.x4.shared.b16 {%0,%1,%2,%3}, [%4];"
                             : "=r"(bf[h][0]), "=r"(bf[h][1]), "=r"(bf[h][2]), "=r"(bf[h][3]) : "r"(p));
            }
            #pragma unroll
            for (int fi = 0; fi < 2; fi++) {
                uint32_t a0, a1, a2, a3;
                int row = wm + fi * 16 + (lane & 15);
                uint32_t p = baseA + row * 128 + ((cl ^ (row & 7)) << 4);
                asm volatile("ldmatrix.sync.aligned.m8n8.x4.shared.b16 {%0,%1,%2,%3}, [%4];"
                             : "=r"(a0), "=r"(a1), "=r"(a2), "=r"(a3) : "r"(p));
                #pragma unroll
                for (int h = 0; h < 2; h++) {
                    asm volatile("mma.sync.aligned.m16n8k16.row.col.f32.f16.f16.f32 "
                                 "{%0,%1,%2,%3}, {%4,%5,%6,%7}, {%8,%9}, {%0,%1,%2,%3};"
                                 : "+f"(c[fi][2*h+0][0]), "+f"(c[fi][2*h+0][1]), "+f"(c[fi][2*h+0][2]), "+f"(c[fi][2*h+0][3])
                                 : "r"(a0), "r"(a1), "r"(a2), "r"(a3), "r"(bf[h][0]), "r"(bf[h][2]));
                    asm volatile("mma.sync.aligned.m16n8k16.row.col.f32.f16.f16.f32 "
                                 "{%0,%1,%2,%3}, {%4,%5,%6,%7}, {%8,%9}, {%0,%1,%2,%3};"
                                 : "+f"(c[fi][2*h+1][0]), "+f"(c[fi][2*h+1][1]), "+f"(c[fi][2*h+1][2]), "+f"(c[fi][2*h+1][3])
                                 : "r"(a0), "r"(a1), "r"(a2), "r"(a3), "r"(bf[h][1]), "r"(bf[h][3]));
                }
            }
        }
    };

    issue(0);
    if (nch > 1) issue(1);
    for (int ch = 0; ch < nch; ch++) {
        if (ch + 1 < nch) asm volatile("cp.async.wait_group 1;" ::: "memory");
        else              asm volatile("cp.async.wait_group 0;" ::: "memory");
        __syncthreads();
        compute(ch & 1);
        __syncthreads();
        if (ch + 2 < nch) issue(ch + 2);
    }

    // ---- epilogue ----
    __half* dst;
    int stride, cb;
    if (OUTMODE == 1) {
        dst    = useB ? out1 : out0;
        stride = useB ? 512 : 256;
        cb     = nb;
    } else {
        dst    = out0;
        stride = ostride;
        cb     = bn;
    }
    #pragma unroll
    for (int fi = 0; fi < 2; fi++) {
        int row0 = bm + wm + fi * 16 + (lane >> 2);
        #pragma unroll
        for (int nj = 0; nj < 4; nj++) {
            int cl = wn + nj * 8 + (lane & 3) * 2;
            float bx = 0.f, by = 0.f;
            if (OUTMODE == 1) { bx = bias[bn + cl]; by = bias[bn + cl + 1]; }
            float v0 = c[fi][nj][0] + bx, v1 = c[fi][nj][1] + by;
            float v2 = c[fi][nj][2] + bx, v3 = c[fi][nj][3] + by;
            int col = cb + cl;
            if (row0 < M)
                *reinterpret_cast<__half2*>(&dst[(size_t)row0 * stride + col]) = __floats2half2_rn(v0, v1);
            if (row0 + 8 < M)
                *reinterpret_cast<__half2*>(&dst[(size_t)(row0 + 8) * stride + col]) = __floats2half2_rn(v2, v3);
        }
    }
}

// Batched Wc precompute: Wc[l] = Ws_uniform[l](split) @ WlT[l]  -> fp16 [512, K_l]
__global__ void __launch_bounds__(256) wc_gemm() {
    int l  = blockIdx.z;
    int bn = blockIdx.y * 64;
    int nout = (l == 0) ? 64 : 256;
    if (bn >= nout) return;
    gemm_core<2, false>(g_Wshi[l], g_Wslo[l], g_WlThi[l], nullptr,
                        nullptr, g_Wchi[l], nullptr, 512, 256, nout,
                        blockIdx.x * 128, bn);
}

// Fused per-layer GEMM: [Hhi | AB] = relu_in @ [Wlin ; Wc]^T + b768
__global__ void __launch_bounds__(256) layer_gemm(
    const __half* __restrict__ Ahi, const __half* __restrict__ Alo,
    int l, int K, __half* __restrict__ Hhi, __half* __restrict__ AB)
{
    gemm_core<1, true>(Ahi, Alo, g_Wlhi[l], g_Wchi[l],
                       g_b768[l], Hhi, AB, NNODES, K, 0,
                       blockIdx.x * 128, blockIdx.y * 64);
}

// ============================================================================
// Fused score + aggregate: one warp per dst node (CSR), no atomics.
// 2-edge ILP. MODE 0: relu-split hi/lo fp16 out. MODE 1: fp32 out (final).
// ============================================================================
template<int MODE>
__global__ void __launch_bounds__(256) agg_kernel(
    const __half* __restrict__ AB,
    const __half* __restrict__ Hhi,
    const float* __restrict__ w2, const float* __restrict__ b2,
    float* __restrict__ outf, __half* __restrict__ ohi, __half* __restrict__ olo)
{
    const int lane = threadIdx.x & 31;
    const int d    = blockIdx.x * (blockDim.x >> 5) + (threadIdx.x >> 5);
    if (d >= NNODES) return;

    const float4 w0 = *reinterpret_cast<const float4*>(&w2[lane * 8]);
    const float4 w1 = *reinterpret_cast<const float4*>(&w2[lane * 8 + 4]);
    const float  bb = b2[0];

    uint4 araw = *reinterpret_cast<const uint4*>(&AB[(size_t)d * (2 * CH) + lane * 8]);
    float2 a0 = __half22float2(*reinterpret_cast<__half2*>(&araw.x));
    float2 a1 = __half22float2(*reinterpret_cast<__half2*>(&araw.y));
    float2 a2 = __half22float2(*reinterpret_cast<__half2*>(&araw.z));
    float2 a3 = __half22float2(*reinterpret_cast<__half2*>(&araw.w));

    float acc0 = 0.f, acc1 = 0.f, acc2 = 0.f, acc3 = 0.f;
    float acc4 = 0.f, acc5 = 0.f, acc6 = 0.f, acc7 = 0.f;

    auto partial = [&](int s, uint4& hraw) -> float {
        uint4 braw = *reinterpret_cast<const uint4*>(&AB[(size_t)s * (2 * CH) + CH + lane * 8]);
        hraw = *reinterpret_cast<const uint4*>(&Hhi[(size_t)s * CH + lane * 8]);
        float2 b0 = __half22float2(*reinterpret_cast<__half2*>(&braw.x));
        float2 b1 = __half22float2(*reinterpret_cast<__half2*>(&braw.y));
        float2 b2v = __half22float2(*reinterpret_cast<__half2*>(&braw.z));
        float2 b3 = __half22float2(*reinterpret_cast<__half2*>(&braw.w));
        float p;
        p  = fmaxf(a0.x + b0.x, 0.f) * w0.x;
        p += fmaxf(a0.y + b0.y, 0.f) * w0.y;
        p += fmaxf(a1.x + b1.x, 0.f) * w0.z;
        p += fmaxf(a1.y + b1.y, 0.f) * w0.w;
        p += fmaxf(a2.x + b2v.x, 0.f) * w1.x;
        p += fmaxf(a2.y + b2v.y, 0.f) * w1.y;
        p += fmaxf(a3.x + b3.x, 0.f) * w1.z;
        p += fmaxf(a3.y + b3.y, 0.f) * w1.w;
        return p;
    };

    auto accum = [&](float score, const uint4& hraw) {
        float2 h0 = __half22float2(*reinterpret_cast<const __half2*>(&hraw.x));
        float2 h1 = __half22float2(*reinterpret_cast<const __half2*>(&hraw.y));
        float2 h2 = __half22float2(*reinterpret_cast<const __half2*>(&hraw.z));
        float2 h3 = __half22float2(*reinterpret_cast<const __half2*>(&hraw.w));
        acc0 = fmaf(score, h0.x, acc0);
        acc1 = fmaf(score, h0.y, acc1);
        acc2 = fmaf(score, h1.x, acc2);
        acc3 = fmaf(score, h1.y, acc3);
        acc4 = fmaf(score, h2.x, acc4);
        acc5 = fmaf(score, h2.y, acc5);
        acc6 = fmaf(score, h3.x, acc6);
        acc7 = fmaf(score, h3.y, acc7);
    };

    const int beg = g_rowptr[d];
    const int end = g_rowptr[d + 1];

    // self-loop first
    {
        uint4 hraw;
        float p = partial(d, hraw);
        #pragma unroll
        for (int off = 16; off > 0; off >>= 1)
            p += __shfl_xor_sync(0xffffffffu, p, off);
        accum(1.f / (1.f + __expf(-(p + bb))), hraw);
    }

    int i = beg;
    for (; i + 1 < end; i += 2) {
        int s0 = g_col[i];
        int s1 = g_col[i + 1];
        uint4 hraw0, hraw1;
        float p0 = partial(s0, hraw0);
        float p1 = partial(s1, hraw1);
        #pragma unroll
        for (int off = 16; off > 0; off >>= 1) {
            p0 += __shfl_xor_sync(0xffffffffu, p0, off);
            p1 += __shfl_xor_sync(0xffffffffu, p1, off);
        }
        float sc0 = 1.f / (1.f + __expf(-(p0 + bb)));
        float sc1 = 1.f / (1.f + __expf(-(p1 + bb)));
        accum(sc0, hraw0);
        accum(sc1, hraw1);
    }
    if (i < end) {
        uint4 hraw;
        float p = partial(g_col[i], hraw);
        #pragma unroll
        for (int off = 16; off > 0; off >>= 1)
            p += __shfl_xor_sync(0xffffffffu, p, off);
        accum(1.f / (1.f + __expf(-(p + bb))), hraw);
    }

    if (MODE == 1) {
        float* op = &outf[(size_t)d * CH + lane * 8];
        *reinterpret_cast<float4*>(op)     = make_float4(acc0, acc1, acc2, acc3);
        *reinterpret_cast<float4*>(op + 4) = make_float4(acc4, acc5, acc6, acc7);
    } else {
        float r[8] = {fmaxf(acc0, 0.f), fmaxf(acc1, 0.f), fmaxf(acc2, 0.f), fmaxf(acc3, 0.f),
                      fmaxf(acc4, 0.f), fmaxf(acc5, 0.f), fmaxf(acc6, 0.f), fmaxf(acc7, 0.f)};
        __half h[8], l[8];
        #pragma unroll
        for (int q = 0; q < 8; q++) {
            h[q] = __float2half_rn(r[q]);
            l[q] = __float2half_rn(r[q] - __half2float(h[q]));
        }
        uint4 hv, lv;
        hv.x = *reinterpret_cast<unsigned*>(&__halves2half2(h[0], h[1]));
        hv.y = *reinterpret_cast<unsigned*>(&__halves2half2(h[2], h[3]));
        hv.z = *reinterpret_cast<unsigned*>(&__halves2half2(h[4], h[5]));
        hv.w = *reinterpret_cast<unsigned*>(&__halves2half2(h[6], h[7]));
        lv.x = *reinterpret_cast<unsigned*>(&__halves2half2(l[0], l[1]));
        lv.y = *reinterpret_cast<unsigned*>(&__halves2half2(l[2], l[3]));
        lv.z = *reinterpret_cast<unsigned*>(&__halves2half2(l[4], l[5]));
        lv.w = *reinterpret_cast<unsigned*>(&__halves2half2(l[6], l[7]));
        *reinterpret_cast<uint4*>(&ohi[(size_t)d * CH + lane * 8]) = hv;
        *reinterpret_cast<uint4*>(&olo[(size_t)d * CH + lane * 8]) = lv;
    }
}

extern "C" void kernel_launch(void* const* d_in, const int* in_sizes, int n_in,
                              void* d_out, int out_size)
{
    (void)in_sizes; (void)n_in; (void)out_size;
    const float* x  = (const float*)d_in[0];
    const int*   ei = (const int*)d_in[1];
    const float* W_lin[3] = {(const float*)d_in[2],  (const float*)d_in[8],  (const float*)d_in[14]};
    const float* b_lin[3] = {(const float*)d_in[3],  (const float*)d_in[9],  (const float*)d_in[15]};
    const float* W_s1[3]  = {(const float*)d_in[4],  (const float*)d_in[10], (const float*)d_in[16]};
    const float* b_s1[3]  = {(const float*)d_in[5],  (const float*)d_in[11], (const float*)d_in[17]};
    const float* W_s2[3]  = {(const float*)d_in[6],  (const float*)d_in[12], (const float*)d_in[18]};
    const float* b_s2[3]  = {(const float*)d_in[7],  (const float*)d_in[13], (const float*)d_in[19]};

    __half *xhi, *xlo, *Hhi, *Ahi, *Alo, *AB;
    cudaGetSymbolAddress((void**)&xhi, g_xhi);
    cudaGetSymbolAddress((void**)&xlo, g_xlo);
    cudaGetSymbolAddress((void**)&Hhi, g_Hhi);
    cudaGetSymbolAddress((void**)&Ahi, g_Ahi);
    cudaGetSymbolAddress((void**)&Alo, g_Alo);
    cudaGetSymbolAddress((void**)&AB,  g_AB);
    float* out = (float*)d_out;

    const dim3 blk(256);
    const dim3 gL((NNODES + 127) / 128, 768 / 64);   // (79, 12)
    const dim3 gWc(4, 4, 3);
    const int  agrid = (NNODES + 7) / 8;

    // ---- one-shot prep (conversions + bias + dst histogram) ----
    cvt_all<<<(S_END + 255) / 256, blk>>>(x, ei, W_lin[0], W_lin[1], W_lin[2],
                                          W_s1[0], W_s1[1], W_s1[2],
                                          b_lin[0], b_lin[1], b_lin[2],
                                          b_s1[0], b_s1[1], b_s1[2]);
    wc_gemm<<<gWc, blk>>>();

    // ---- CSR finish ----
    scan_kernel<<<1, 1024>>>();
    scatter_kernel<<<(NEDGES + 255) / 256, blk>>>(ei);

    // ---- layer 1 ----
    layer_gemm<<<gL, blk>>>(xhi, xlo, 0, 64, Hhi, AB);
    agg_kernel<0><<<agrid, blk>>>(AB, Hhi, W_s2[0], b_s2[0], nullptr, Ahi, Alo);

    // ---- layer 2 ----
    layer_gemm<<<gL, blk>>>(Ahi, Alo, 1, 256, Hhi, AB);
    agg_kernel<0><<<agrid, blk>>>(AB, Hhi, W_s2[1], b_s2[1], nullptr, Ahi, Alo);

    // ---- layer 3 (writes d_out) ----
    layer_gemm<<<gL, blk>>>(Ahi, Alo, 2, 256, Hhi, AB);
    agg_kernel<1><<<agrid, blk>>>(AB, Hhi, W_s2[2], b_s2[2], out, nullptr, nullptr);
}

// round 11
// speedup vs baseline: 1.4161x; 1.0271x over previous
#include <cuda_runtime.h>
#include <cuda_fp16.h>
#include <cstdint>

#define NNODES 10000
#define NEDGES 320000
#define CH     256

// ---- scratch (static device allocations; no cudaMalloc allowed) ----
__device__ __align__(16) __half g_xhi[NNODES * 64];
__device__ __align__(16) __half g_xlo[NNODES * 64];
__device__ __align__(16) __half g_Hhi[NNODES * CH];
__device__ __align__(16) __half g_Ahi[NNODES * CH];   // relu(agg) split, next-layer input
__device__ __align__(16) __half g_Alo[NNODES * CH];
__device__ __align__(16) __half g_AB [NNODES * 2 * CH];
__device__ __align__(16) __half g_Wlhi[3][CH * CH];       // W_lin fp16 (layer0: 256x64)
__device__ __align__(16) __half g_WlThi[3][CH * CH];      // W_lin^T fp16 (rows k_in, cols m)
__device__ __align__(16) __half g_Wshi[3][2 * CH * CH];   // W_s1 uniform [512,256] split
__device__ __align__(16) __half g_Wslo[3][2 * CH * CH];
__device__ __align__(16) __half g_Wchi[3][2 * CH * CH];   // Wc = Ws @ Wlin  [512, K_l] fp16
__device__ float g_b768[3][768];                          // [b_lin | Ws@b_lin + b_s1pad]
__device__ int g_rowptr[NNODES + 1];
__device__ int g_cnt[NNODES];   // starts 0; hist fills; scatter's atomicSub restores to 0
__device__ int g_col[NEDGES];

__device__ __forceinline__ uint32_t sptr(const void* p) {
    return (uint32_t)__cvta_generic_to_shared(p);
}
__device__ __forceinline__ void cpa16(uint32_t dst, const void* src, bool pred) {
    int sz = pred ? 16 : 0;
    asm volatile("cp.async.cg.shared.global [%0], [%1], 16, %2;"
                 :: "r"(dst), "l"(src), "r"(sz));
}
__device__ __forceinline__ void cpa_commit() {
    asm volatile("cp.async.commit_group;" ::: "memory");
}

// ============================================================================
// ONE fused prep kernel: x split, Wlin fp16, Wlin^T fp16, Ws uniform split,
// fused bias b768, AND the dst histogram (g_cnt starts at 0 — restored by
// scatter's atomicSub on the previous launch/replay).
// ============================================================================
#define CX    (NNODES * 64)
#define S_WL0 (CX)
#define S_WL1 (S_WL0 + 16384)
#define S_WL2 (S_WL1 + 65536)
#define S_WT0 (S_WL2 + 65536)
#define S_WT1 (S_WT0 + 16384)
#define S_WT2 (S_WT1 + 65536)
#define S_WS0 (S_WT2 + 65536)
#define S_WS1 (S_WS0 + 131072)
#define S_WS2 (S_WS1 + 131072)
#define S_BIA (S_WS2 + 131072)
#define S_HST (S_BIA + 3 * 768)
#define S_END (S_HST + NEDGES)

__global__ void __launch_bounds__(256) cvt_all(
    const float* __restrict__ x, const int* __restrict__ ei,
    const float* __restrict__ Wl1, const float* __restrict__ Wl2, const float* __restrict__ Wl3,
    const float* __restrict__ Ws1, const float* __restrict__ Ws2, const float* __restrict__ Ws3,
    const float* __restrict__ bl1, const float* __restrict__ bl2, const float* __restrict__ bl3,
    const float* __restrict__ bs1, const float* __restrict__ bs2, const float* __restrict__ bs3)
{
    int i = blockIdx.x * blockDim.x + threadIdx.x;
    if (i >= S_END) return;
    if (i < CX) {
        float v = x[i];
        __half h = __float2half_rn(v);
        g_xhi[i] = h;
        g_xlo[i] = __float2half_rn(v - __half2float(h));
        return;
    }
    if (i < S_WT0) {   // Wlin fp16 copy
        int l, j; const float* W;
        if (i < S_WL1)      { l = 0; j = i - S_WL0; W = Wl1; }
        else if (i < S_WL2) { l = 1; j = i - S_WL1; W = Wl2; }
        else                { l = 2; j = i - S_WL2; W = Wl3; }
        g_Wlhi[l][j] = __float2half_rn(W[j]);
        return;
    }
    if (i < S_WS0) {   // Wlin^T fp16: [k_in][m] from Wlin[m*kin + k]
        int l, j, kin; const float* W;
        if (i < S_WT1)      { l = 0; j = i - S_WT0; W = Wl1; kin = 64; }
        else if (i < S_WT2) { l = 1; j = i - S_WT1; W = Wl2; kin = 256; }
        else                { l = 2; j = i - S_WT2; W = Wl3; kin = 256; }
        int k = j >> 8, m = j & 255;
        g_WlThi[l][j] = __float2half_rn(W[m * kin + k]);
        return;
    }
    if (i < S_BIA) {   // Ws uniform repack + hi/lo split
        int l, j; const float* W;
        if (i < S_WS1)      { l = 0; j = i - S_WS0; W = Ws1; }
        else if (i < S_WS2) { l = 1; j = i - S_WS1; W = Ws2; }
        else                { l = 2; j = i - S_WS2; W = Ws3; }
        int r = j >> 8, k = j & 255;
        float v = (r < CH) ? W[r * 2 * CH + k] : W[(r - CH) * 2 * CH + CH + k];
        __half h = __float2half_rn(v);
        g_Wshi[l][j] = h;
        g_Wslo[l][j] = __float2half_rn(v - __half2float(h));
        return;
    }
    if (i < S_HST) {   // fused bias: b768[l] = [b_lin | Ws@b_lin + b_s1pad]
        int q = i - S_BIA;
        int l = q / 768, j = q % 768;
        const float* bl = (l == 0) ? bl1 : (l == 1) ? bl2 : bl3;
        const float* Ws = (l == 0) ? Ws1 : (l == 1) ? Ws2 : Ws3;
        const float* bs = (l == 0) ? bs1 : (l == 1) ? bs2 : bs3;
        if (j < 256) { g_b768[l][j] = bl[j]; return; }
        int r = j - 256;
        float acc = (r < CH) ? bs[r] : 0.f;
        for (int m = 0; m < 256; m++) {
            float w = (r < CH) ? Ws[r * 2 * CH + m] : Ws[(r - CH) * 2 * CH + CH + m];
            acc += w * bl[m];
        }
        g_b768[l][j] = acc;
        return;
    }
    // dst histogram
    atomicAdd(&g_cnt[ei[NEDGES + (i - S_HST)]], 1);
}

// ============================================================================
// Single-pass scan: 1024 threads x 10 elements, 2 barriers total.
// Does NOT modify g_cnt (scatter restores it to zero).
// ============================================================================
__global__ void __launch_bounds__(1024) scan_kernel() {
    __shared__ int wsum[32];
    const int t = threadIdx.x, lane = t & 31, w = t >> 5;
    const int base_i = t * 10;
    int v[10];
    int s = 0;
    #pragma unroll
    for (int q = 0; q < 10; q++) {
        int idx = base_i + q;
        v[q] = (idx < NNODES) ? g_cnt[idx] : 0;
        s += v[q];
    }
    int x = s;
    #pragma unroll
    for (int o = 1; o < 32; o <<= 1) {
        int y = __shfl_up_sync(0xffffffffu, x, o);
        if (lane >= o) x += y;
    }
    if (lane == 31) wsum[w] = x;
    __syncthreads();
    if (w == 0) {
        int z = wsum[lane];
        #pragma unroll
        for (int o = 1; o < 32; o <<= 1) {
            int y = __shfl_up_sync(0xffffffffu, z, o);
            if (lane >= o) z += y;
        }
        wsum[lane] = z;
    }
    __syncthreads();
    int run = (x - s) + (w > 0 ? wsum[w - 1] : 0);   // exclusive prefix for this thread
    #pragma unroll
    for (int q = 0; q < 10; q++) {
        int idx = base_i + q;
        if (idx < NNODES) g_rowptr[idx] = run;
        run += v[q];
    }
    if (t == 1023) g_rowptr[NNODES] = wsum[31];
}

// scatter restores g_cnt to all-zero (atomicSub), keeping replays deterministic.
__global__ void scatter_kernel(const int* __restrict__ ei) {
    int e = blockIdx.x * blockDim.x + threadIdx.x;
    if (e < NEDGES) {
        int s = ei[e];
        int d = ei[NEDGES + e];
        int old = atomicSub(&g_cnt[d], 1);
        g_col[g_rowptr[d] + old - 1] = s;
    }
}

// ============================================================================
// GEMM core: 2-region split (A = hi+lo exact vs fp16 W; W fp16 single).
// Virtual K' = 2K over regions: (Ahi,W), (Alo,W).
// BM=128 BN=64 BK=64, 8 warps, warp tile 32x32 (4M x 2N), 2-stage cp.async,
// 128B-row XOR swizzle.
// DUALW: weight rows n<256 from Wa, n>=256 from Wb (both stride K).
// OUTMODE 1: dual single-fp16 out (n<256 -> out0 stride 256, else out1 stride 512), +bias.
// OUTMODE 2: single fp16 out0 stride ostride, no bias.
// ============================================================================
template<int OUTMODE, bool DUALW>
__device__ __forceinline__ void gemm_core(
    const __half* __restrict__ Ahi, const __half* __restrict__ Alo,
    const __half* __restrict__ Wahi, const __half* __restrict__ Wbhi,
    const float* __restrict__ bias,
    __half* __restrict__ out0, __half* __restrict__ out1,
    int M, int K, int ostride, int bm, int bn)
{
    constexpr int BM = 128, BN = 64, BK = 64;
    __shared__ __align__(16) __half sA[2][BM * BK];   // 32 KB
    __shared__ __align__(16) __half sB[2][BN * BK];   // 16 KB

    const int tid  = threadIdx.x;
    const int lane = tid & 31;
    const int warp = tid >> 5;
    const int wm   = (warp >> 1) * 32;
    const int wn   = (warp & 1) * 32;
    const int nch  = (2 * K) / BK;

    const int chunk = tid & 7;
    const int rbase = tid >> 3;

    const bool useB = DUALW && (bn >= 256);
    const int  nb   = useB ? bn - 256 : bn;
    const __half* Whi = useB ? Wbhi : Wahi;

    float c[2][4][4];
    #pragma unroll
    for (int i = 0; i < 2; i++)
        #pragma unroll
        for (int j = 0; j < 4; j++)
            #pragma unroll
            for (int q = 0; q < 4; q++) c[i][j][q] = 0.f;

    auto issue = [&](int ch) {
        int buf = ch & 1;
        int k0v = ch * BK;
        int region = k0v / K;
        int kreal  = k0v - region * K;
        const __half* As = (region == 1) ? Alo : Ahi;
        uint32_t baseA = sptr(&sA[buf][0]);
        uint32_t baseB = sptr(&sB[buf][0]);
        #pragma unroll
        for (int i = 0; i < 4; i++) {
            int row = rbase + 32 * i;
            int gm  = bm + row;
            bool ok = gm < M;
            const __half* src = As + (size_t)(ok ? gm : 0) * K + kreal + chunk * 8;
            cpa16(baseA + row * 128 + ((chunk ^ (row & 7)) << 4), src, ok);
        }
        #pragma unroll
        for (int i = 0; i < 2; i++) {
            int row = rbase + 32 * i;
            const __half* src = Whi + (size_t)(nb + row) * K + kreal + chunk * 8;
            cpa16(baseB + row * 128 + ((chunk ^ (row & 7)) << 4), src, true);
        }
        cpa_commit();
    };

    auto compute = [&](int buf) {
        uint32_t baseA = sptr(&sA[buf][0]);
        uint32_t baseB = sptr(&sB[buf][0]);
        #pragma unroll
        for (int kk = 0; kk < 4; kk++) {
            int cl = kk * 2 + (lane >> 4);
            uint32_t bf[2][4];
            #pragma unroll
            for (int h = 0; h < 2; h++) {
                int row = wn + h * 16 + (lane & 15);
                uint32_t p = baseB + row * 128 + ((cl ^ (row & 7)) << 4);
                asm volatile("ldmatrix.sync.aligned.m8n8.x4.shared.b16 {%0,%1,%2,%3}, [%4];"
                             : "=r"(bf[h][0]), "=r"(bf[h][1]), "=r"(bf[h][2]), "=r"(bf[h][3]) : "r"(p));
            }
            #pragma unroll
            for (int fi = 0; fi < 2; fi++) {
                uint32_t a0, a1, a2, a3;
                int row = wm + fi * 16 + (lane & 15);
                uint32_t p = baseA + row * 128 + ((cl ^ (row & 7)) << 4);
                asm volatile("ldmatrix.sync.aligned.m8n8.x4.shared.b16 {%0,%1,%2,%3}, [%4];"
                             : "=r"(a0), "=r"(a1), "=r"(a2), "=r"(a3) : "r"(p));
                #pragma unroll
                for (int h = 0; h < 2; h++) {
                    asm volatile("mma.sync.aligned.m16n8k16.row.col.f32.f16.f16.f32 "
                                 "{%0,%1,%2,%3}, {%4,%5,%6,%7}, {%8,%9}, {%0,%1,%2,%3};"
                                 : "+f"(c[fi][2*h+0][0]), "+f"(c[fi][2*h+0][1]), "+f"(c[fi][2*h+0][2]), "+f"(c[fi][2*h+0][3])
                                 : "r"(a0), "r"(a1), "r"(a2), "r"(a3), "r"(bf[h][0]), "r"(bf[h][2]));
                    asm volatile("mma.sync.aligned.m16n8k16.row.col.f32.f16.f16.f32 "
                                 "{%0,%1,%2,%3}, {%4,%5,%6,%7}, {%8,%9}, {%0,%1,%2,%3};"
                                 : "+f"(c[fi][2*h+1][0]), "+f"(c[fi][2*h+1][1]), "+f"(c[fi][2*h+1][2]), "+f"(c[fi][2*h+1][3])
                                 : "r"(a0), "r"(a1), "r"(a2), "r"(a3), "r"(bf[h][1]), "r"(bf[h][3]));
                }
            }
        }
    };

    issue(0);
    if (nch > 1) issue(1);
    for (int ch = 0; ch < nch; ch++) {
        if (ch + 1 < nch) asm volatile("cp.async.wait_group 1;" ::: "memory");
        else              asm volatile("cp.async.wait_group 0;" ::: "memory");
        __syncthreads();
        compute(ch & 1);
        __syncthreads();
        if (ch + 2 < nch) issue(ch + 2);
    }

    // ---- epilogue ----
    __half* dst;
    int stride, cb;
    if (OUTMODE == 1) {
        dst    = useB ? out1 : out0;
        stride = useB ? 512 : 256;
        cb     = nb;
    } else {
        dst    = out0;
        stride = ostride;
        cb     = bn;
    }
    #pragma unroll
    for (int fi = 0; fi < 2; fi++) {
        int row0 = bm + wm + fi * 16 + (lane >> 2);
        #pragma unroll
        for (int nj = 0; nj < 4; nj++) {
            int cl = wn + nj * 8 + (lane & 3) * 2;
            float bx = 0.f, by = 0.f;
            if (OUTMODE == 1) { bx = bias[bn + cl]; by = bias[bn + cl + 1]; }
            float v0 = c[fi][nj][0] + bx, v1 = c[fi][nj][1] + by;
            float v2 = c[fi][nj][2] + bx, v3 = c[fi][nj][3] + by;
            int col = cb + cl;
            if (row0 < M)
                *reinterpret_cast<__half2*>(&dst[(size_t)row0 * stride + col]) = __floats2half2_rn(v0, v1);
            if (row0 + 8 < M)
                *reinterpret_cast<__half2*>(&dst[(size_t)(row0 + 8) * stride + col]) = __floats2half2_rn(v2, v3);
        }
    }
}

// Batched Wc precompute: Wc[l] = Ws_uniform[l](split) @ WlT[l]  -> fp16 [512, K_l]
__global__ void __launch_bounds__(256) wc_gemm() {
    int l  = blockIdx.z;
    int bn = blockIdx.y * 64;
    int nout = (l == 0) ? 64 : 256;
    if (bn >= nout) return;
    gemm_core<2, false>(g_Wshi[l], g_Wslo[l], g_WlThi[l], nullptr,
                        nullptr, g_Wchi[l], nullptr, 512, 256, nout,
                        blockIdx.x * 128, bn);
}

// Fused per-layer GEMM: [Hhi | AB] = relu_in @ [Wlin ; Wc]^T + b768
__global__ void __launch_bounds__(256) layer_gemm(
    const __half* __restrict__ Ahi, const __half* __restrict__ Alo,
    int l, int K, __half* __restrict__ Hhi, __half* __restrict__ AB)
{
    gemm_core<1, true>(Ahi, Alo, g_Wlhi[l], g_Wchi[l],
                       g_b768[l], Hhi, AB, NNODES, K, 0,
                       blockIdx.x * 128, blockIdx.y * 64);
}

// ============================================================================
// Fused score + aggregate: one warp per dst node (CSR), no atomics.
// 2-edge ILP. MODE 0: relu-split hi/lo fp16 out. MODE 1: fp32 out (final).
// ============================================================================
template<int MODE>
__global__ void __launch_bounds__(256) agg_kernel(
    const __half* __restrict__ AB,
    const __half* __restrict__ Hhi,
    const float* __restrict__ w2, const float* __restrict__ b2,
    float* __restrict__ outf, __half* __restrict__ ohi, __half* __restrict__ olo)
{
    const int lane = threadIdx.x & 31;
    const int d    = blockIdx.x * (blockDim.x >> 5) + (threadIdx.x >> 5);
    if (d >= NNODES) return;

    const float4 w0 = *reinterpret_cast<const float4*>(&w2[lane * 8]);
    const float4 w1 = *reinterpret_cast<const float4*>(&w2[lane * 8 + 4]);
    const float  bb = b2[0];

    uint4 araw = *reinterpret_cast<const uint4*>(&AB[(size_t)d * (2 * CH) + lane * 8]);
    float2 a0 = __half22float2(*reinterpret_cast<__half2*>(&araw.x));
    float2 a1 = __half22float2(*reinterpret_cast<__half2*>(&araw.y));
    float2 a2 = __half22float2(*reinterpret_cast<__half2*>(&araw.z));
    float2 a3 = __half22float2(*reinterpret_cast<__half2*>(&araw.w));

    float acc0 = 0.f, acc1 = 0.f, acc2 = 0.f, acc3 = 0.f;
    float acc4 = 0.f, acc5 = 0.f, acc6 = 0.f, acc7 = 0.f;

    auto partial = [&](int s, uint4& hraw) -> float {
        uint4 braw = *reinterpret_cast<const uint4*>(&AB[(size_t)s * (2 * CH) + CH + lane * 8]);
        hraw = *reinterpret_cast<const uint4*>(&Hhi[(size_t)s * CH + lane * 8]);
        float2 b0 = __half22float2(*reinterpret_cast<__half2*>(&braw.x));
        float2 b1 = __half22float2(*reinterpret_cast<__half2*>(&braw.y));
        float2 b2v = __half22float2(*reinterpret_cast<__half2*>(&braw.z));
        float2 b3 = __half22float2(*reinterpret_cast<__half2*>(&braw.w));
        float p;
        p  = fmaxf(a0.x + b0.x, 0.f) * w0.x;
        p += fmaxf(a0.y + b0.y, 0.f) * w0.y;
        p += fmaxf(a1.x + b1.x, 0.f) * w0.z;
        p += fmaxf(a1.y + b1.y, 0.f) * w0.w;
        p += fmaxf(a2.x + b2v.x, 0.f) * w1.x;
        p += fmaxf(a2.y + b2v.y, 0.f) * w1.y;
        p += fmaxf(a3.x + b3.x, 0.f) * w1.z;
        p += fmaxf(a3.y + b3.y, 0.f) * w1.w;
        return p;
    };

    auto accum = [&](float score, const uint4& hraw) {
        float2 h0 = __half22float2(*reinterpret_cast<const __half2*>(&hraw.x));
        float2 h1 = __half22float2(*reinterpret_cast<const __half2*>(&hraw.y));
        float2 h2 = __half22float2(*reinterpret_cast<const __half2*>(&hraw.z));
        float2 h3 = __half22float2(*reinterpret_cast<const __half2*>(&hraw.w));
        acc0 = fmaf(score, h0.x, acc0);
        acc1 = fmaf(score, h0.y, acc1);
        acc2 = fmaf(score, h1.x, acc2);
        acc3 = fmaf(score, h1.y, acc3);
        acc4 = fmaf(score, h2.x, acc4);
        acc5 = fmaf(score, h2.y, acc5);
        acc6 = fmaf(score, h3.x, acc6);
        acc7 = fmaf(score, h3.y, acc7);
    };

    const int beg = g_rowptr[d];
    const int end = g_rowptr[d + 1];

    // self-loop first
    {
        uint4 hraw;
        float p = partial(d, hraw);
        #pragma unroll
        for (int off = 16; off > 0; off >>= 1)
            p += __shfl_xor_sync(0xffffffffu, p, off);
        accum(1.f / (1.f + __expf(-(p + bb))), hraw);
    }

    int i = beg;
    for (; i + 1 < end; i += 2) {
        int s0 = g_col[i];
        int s1 = g_col[i + 1];
        uint4 hraw0, hraw1;
        float p0 = partial(s0, hraw0);
        float p1 = partial(s1, hraw1);
        #pragma unroll
        for (int off = 16; off > 0; off >>= 1) {
            p0 += __shfl_xor_sync(0xffffffffu, p0, off);
            p1 += __shfl_xor_sync(0xffffffffu, p1, off);
        }
        float sc0 = 1.f / (1.f + __expf(-(p0 + bb)));
        float sc1 = 1.f / (1.f + __expf(-(p1 + bb)));
        accum(sc0, hraw0);
        accum(sc1, hraw1);
    }
    if (i < end) {
        uint4 hraw;
        float p = partial(g_col[i], hraw);
        #pragma unroll
        for (int off = 16; off > 0; off >>= 1)
            p += __shfl_xor_sync(0xffffffffu, p, off);
        accum(1.f / (1.f + __expf(-(p + bb))), hraw);
    }

    if (MODE == 1) {
        float* op = &outf[(size_t)d * CH + lane * 8];
        *reinterpret_cast<float4*>(op)     = make_float4(acc0, acc1, acc2, acc3);
        *reinterpret_cast<float4*>(op + 4) = make_float4(acc4, acc5, acc6, acc7);
    } else {
        float r[8] = {fmaxf(acc0, 0.f), fmaxf(acc1, 0.f), fmaxf(acc2, 0.f), fmaxf(acc3, 0.f),
                      fmaxf(acc4, 0.f), fmaxf(acc5, 0.f), fmaxf(acc6, 0.f), fmaxf(acc7, 0.f)};
        __half h[8], l[8];
        #pragma unroll
        for (int q = 0; q < 8; q++) {
            h[q] = __float2half_rn(r[q]);
            l[q] = __float2half_rn(r[q] - __half2float(h[q]));
        }
        uint4 hv, lv;
        hv.x = *reinterpret_cast<unsigned*>(&__halves2half2(h[0], h[1]));
        hv.y = *reinterpret_cast<unsigned*>(&__halves2half2(h[2], h[3]));
        hv.z = *reinterpret_cast<unsigned*>(&__halves2half2(h[4], h[5]));
        hv.w = *reinterpret_cast<unsigned*>(&__halves2half2(h[6], h[7]));
        lv.x = *reinterpret_cast<unsigned*>(&__halves2half2(l[0], l[1]));
        lv.y = *reinterpret_cast<unsigned*>(&__halves2half2(l[2], l[3]));
        lv.z = *reinterpret_cast<unsigned*>(&__halves2half2(l[4], l[5]));
        lv.w = *reinterpret_cast<unsigned*>(&__halves2half2(l[6], l[7]));
        *reinterpret_cast<uint4*>(&ohi[(size_t)d * CH + lane * 8]) = hv;
        *reinterpret_cast<uint4*>(&olo[(size_t)d * CH + lane * 8]) = lv;
    }
}

extern "C" void kernel_launch(void* const* d_in, const int* in_sizes, int n_in,
                              void* d_out, int out_size)
{
    (void)in_sizes; (void)n_in; (void)out_size;
    const float* x  = (const float*)d_in[0];
    const int*   ei = (const int*)d_in[1];
    const float* W_lin[3] = {(const float*)d_in[2],  (const float*)d_in[8],  (const float*)d_in[14]};
    const float* b_lin[3] = {(const float*)d_in[3],  (const float*)d_in[9],  (const float*)d_in[15]};
    const float* W_s1[3]  = {(const float*)d_in[4],  (const float*)d_in[10], (const float*)d_in[16]};
    const float* b_s1[3]  = {(const float*)d_in[5],  (const float*)d_in[11], (const float*)d_in[17]};
    const float* W_s2[3]  = {(const float*)d_in[6],  (const float*)d_in[12], (const float*)d_in[18]};
    const float* b_s2[3]  = {(const float*)d_in[7],  (const float*)d_in[13], (const float*)d_in[19]};

    __half *xhi, *xlo, *Hhi, *Ahi, *Alo, *AB;
    cudaGetSymbolAddress((void**)&xhi, g_xhi);
    cudaGetSymbolAddress((void**)&xlo, g_xlo);
    cudaGetSymbolAddress((void**)&Hhi, g_Hhi);
    cudaGetSymbolAddress((void**)&Ahi, g_Ahi);
    cudaGetSymbolAddress((void**)&Alo, g_Alo);
    cudaGetSymbolAddress((void**)&AB,  g_AB);
    float* out = (float*)d_out;

    const dim3 blk(256);
    const dim3 gL((NNODES + 127) / 128, 768 / 64);   // (79, 12)
    const dim3 gWc(4, 4, 3);
    const int  agrid = (NNODES + 7) / 8;

    // Fork/join resources (host-side objects only; created per call — the
    // graph replays never re-execute host code, and the correctness+capture
    // calls leak only a handful of stream/event handles).
    cudaStream_t side;
    cudaEvent_t  evFork, evJoin;
    cudaStreamCreateWithFlags(&side, cudaStreamNonBlocking);
    cudaEventCreateWithFlags(&evFork, cudaEventDisableTiming);
    cudaEventCreateWithFlags(&evJoin, cudaEventDisableTiming);

    // ---- one-shot prep (conversions + bias + dst histogram) ----
    cvt_all<<<(S_END + 255) / 256, blk>>>(x, ei, W_lin[0], W_lin[1], W_lin[2],
                                          W_s1[0], W_s1[1], W_s1[2],
                                          b_lin[0], b_lin[1], b_lin[2],
                                          b_s1[0], b_s1[1], b_s1[2]);

    // ---- fork: CSR finish on side stream, GEMM prep on main stream ----
    cudaEventRecord(evFork, 0);
    cudaStreamWaitEvent(side, evFork, 0);

    scan_kernel<<<1, 1024, 0, side>>>();
    scatter_kernel<<<(NEDGES + 255) / 256, blk, 0, side>>>(ei);
    cudaEventRecord(evJoin, side);

    wc_gemm<<<gWc, blk>>>();
    layer_gemm<<<gL, blk>>>(xhi, xlo, 0, 64, Hhi, AB);

    // ---- join before the first aggregation (needs g_col/g_rowptr) ----
    cudaStreamWaitEvent(0, evJoin, 0);
    agg_kernel<0><<<agrid, blk>>>(AB, Hhi, W_s2[0], b_s2[0], nullptr, Ahi, Alo);

    // ---- layer 2 ----
    layer_gemm<<<gL, blk>>>(Ahi, Alo, 1, 256, Hhi, AB);
    agg_kernel<0><<<agrid, blk>>>(AB, Hhi, W_s2[1], b_s2[1], nullptr, Ahi, Alo);

    // ---- layer 3 (writes d_out) ----
    layer_gemm<<<gL, blk>>>(Ahi, Alo, 2, 256, Hhi, AB);
    agg_kernel<1><<<agrid, blk>>>(AB, Hhi, W_s2[2], b_s2[2], out, nullptr, nullptr);
}